// round 11
// baseline (speedup 1.0000x reference)
#include <cuda_runtime.h>
#include <cuda_fp16.h>
#include <math.h>
#include <stdint.h>

#define NN   32768
#define CC   128
#define EE   524288
#define BBG  64
#define NGR  512
#define HH   4
#define DH   32
#define KEIG 128
#define KCH  5
#define BN_EPS 1e-5f

// ---------------- static scratch ----------------
__device__ float g_big [NN * 640];
__device__ float g_hid [NN * 2 * CC];
__device__ float g_loc [NN * CC];
__device__ float g_xspec[NN * CC];
__device__ float g_hproj[NN * CC];
__device__ float g_att [NN * CC];
__device__ float g_h2  [NN * CC];
__device__ float g_qkv [NN * 3 * CC];
__device__ float g_S   [KEIG * CC];
__device__ __half g_Sth[KEIG * CC];     // transposed fp16 S
__device__ float g_dis [NN];
__device__ int   g_outdeg[NN];
__device__ int   g_indeg [NN];
__device__ int   g_rowptr[NN + 1];
__device__ int   g_cursor[NN];
__device__ int   g_ecol  [EE];
__device__ int   g_blksum[128];
__device__ int   g_blkoff[128];
__device__ float g_sums[6 * CC];
__device__ float g_ab  [6 * CC];

// fp16 TRANSPOSED weights: layout [Cout][Kd] (element offsets)
#define OSPA1 0
#define OSPA2 16384
#define OSPE1 32768
#define OSPE2 49152
#define OPROJ 65536
#define OCHEB 81920
#define OQKV  163840
#define OWOUT 212992
#define OMLP1 229376
#define OMLP2 262144
#define WTOT  294912
__device__ __half g_wrd[WTOT];

__device__ __forceinline__ float cvt_tf32(float x) {
    float r;
    asm("cvt.rna.tf32.f32 %0, %1;" : "=f"(r) : "f"(x));
    return r;
}
__device__ __forceinline__ float4 cvt_tf32_4(float4 v) {
    v.x = cvt_tf32(v.x); v.y = cvt_tf32(v.y);
    v.z = cvt_tf32(v.z); v.w = cvt_tf32(v.w);
    return v;
}
#define MMA_TF32(d0,d1,d2,d3,a0,a1,a2,a3,b0,b1)                               \
    asm volatile("mma.sync.aligned.m16n8k8.row.col.f32.tf32.tf32.f32 "        \
        "{%0,%1,%2,%3}, {%4,%5,%6,%7}, {%8,%9}, {%0,%1,%2,%3};"               \
        : "+f"(d0), "+f"(d1), "+f"(d2), "+f"(d3)                              \
        : "r"(a0), "r"(a1), "r"(a2), "r"(a3), "r"(b0), "r"(b1))

#define MMA_F16(d0,d1,d2,d3,a0,a1,a2,a3,b0,b1)                                \
    asm volatile("mma.sync.aligned.m16n8k16.row.col.f32.f16.f16.f32 "         \
        "{%0,%1,%2,%3}, {%4,%5,%6,%7}, {%8,%9}, {%0,%1,%2,%3};"               \
        : "+f"(d0), "+f"(d1), "+f"(d2), "+f"(d3)                              \
        : "r"(a0), "r"(a1), "r"(a2), "r"(a3), "r"(b0), "r"(b1))

__device__ __forceinline__ uint32_t packh2(float lo, float hi) {
    __half2 h = __floats2half2_rn(lo, hi);
    return *(uint32_t*)&h;
}

#define CP16(dst32, srcp) \
    asm volatile("cp.async.cg.shared.global [%0], [%1], 16;" :: "r"(dst32), "l"(srcp))
#define CPCOMMIT() asm volatile("cp.async.commit_group;")
#define CPWAIT0()  asm volatile("cp.async.wait_group 0;")
#define CPWAIT1()  asm volatile("cp.async.wait_group 1;")

// ---------------- weight transpose+convert: out[c*K+k] = half(in[k*C+c]) ----
__global__ void k_trw(const float* __restrict__ in, __half* __restrict__ out,
                      int K, int C)
{
    int idx = blockIdx.x * 256 + threadIdx.x;
    if (idx < K * C) {
        int k = idx / C, c = idx - k * C;
        out[c * K + k] = __float2half(in[idx]);
    }
}

// ---------------- graph preprocessing ----------------
__global__ void k_count(const int* __restrict__ src, const int* __restrict__ dst) {
    int e = blockIdx.x * blockDim.x + threadIdx.x;
    if (e < EE) {
        atomicAdd(&g_outdeg[src[e]], 1);
        atomicAdd(&g_indeg [dst[e]], 1);
    }
}

__global__ void k_dis() {
    int n = blockIdx.x * blockDim.x + threadIdx.x;
    if (n < NN) {
        int d = g_outdeg[n];
        g_dis[n] = (d > 0) ? rsqrtf((float)d) : 0.0f;
    }
}

__global__ void k_scan1() {
    __shared__ int sh[256];
    int t = threadIdx.x;
    int i = blockIdx.x * 256 + t;
    int v = g_indeg[i];
    sh[t] = v;
    __syncthreads();
#pragma unroll
    for (int off = 1; off < 256; off <<= 1) {
        int u = (t >= off) ? sh[t - off] : 0;
        __syncthreads();
        sh[t] += u;
        __syncthreads();
    }
    g_rowptr[i] = sh[t] - v;
    if (t == 255) g_blksum[blockIdx.x] = sh[255];
}

__global__ void k_scan2() {
    __shared__ int sh[128];
    int t = threadIdx.x;
    int v = g_blksum[t];
    sh[t] = v;
    __syncthreads();
#pragma unroll
    for (int off = 1; off < 128; off <<= 1) {
        int u = (t >= off) ? sh[t - off] : 0;
        __syncthreads();
        sh[t] += u;
        __syncthreads();
    }
    g_blkoff[t] = sh[t] - v;
    if (t == 127) g_rowptr[NN] = sh[127];
}

__global__ void k_scan3() {
    int t = threadIdx.x;
    int i = blockIdx.x * 256 + t;
    int r = g_rowptr[i] + g_blkoff[blockIdx.x];
    g_rowptr[i] = r;
    g_cursor[i] = r;
}

__global__ void k_fill(const int* __restrict__ src, const int* __restrict__ dst) {
    int e = blockIdx.x * blockDim.x + threadIdx.x;
    if (e < EE) {
        int p = atomicAdd(&g_cursor[dst[e]], 1);
        g_ecol[p] = src[e];
    }
}

// ---------------- fp16 GEMM, cp.async double-buffered, 2 CTAs/SM -------------
// A [M,Kd] fp32 row-major (ldA); Wh [Cout][Kd] fp16 transposed.
#define AS_STR 20
#define A_WORDS (128 * AS_STR)
#define B_HALVES (128 * 24)              // [c][k] stride 24 halves (16 data + 8 pad)
#define B_BYTES  (B_HALVES * 2)
__global__ __launch_bounds__(256, 2) void k_gemm(
    const float* __restrict__ A, const __half* __restrict__ Wh,
    const float* __restrict__ bias, const float* __restrict__ res,
    float* __restrict__ C, int M, int Kd, int ldA, int Cout, int ldC,
    int relu, int accum, float* __restrict__ sums)
{
    __shared__ float  As[2 * A_WORDS];
    __shared__ __half Bs[2 * B_HALVES];
    int bm = blockIdx.x * 128;
    int bn = blockIdx.y * 128;
    int tid = threadIdx.x;
    int warp = tid >> 5, lane = tid & 31;
    int wm = (warp >> 1) * 32;
    int wn = (warp & 1) * 64;
    int lr = lane >> 2;
    int lc = lane & 3;

    uint32_t asB = (uint32_t)__cvta_generic_to_shared(As);
    uint32_t bsB = (uint32_t)__cvta_generic_to_shared(Bs);
    int aRow = tid >> 2, aC4 = (tid & 3) * 4;
    int bC = tid >> 1, bH = tid & 1;

#define GISSUE(buf, k0) do {                                                        \
    CP16(asB + (uint32_t)((buf) * A_WORDS + aRow * AS_STR + aC4) * 4u,              \
         A + (size_t)(bm + aRow) * ldA + (k0) + aC4);                               \
    CP16(asB + (uint32_t)((buf) * A_WORDS + (aRow + 64) * AS_STR + aC4) * 4u,       \
         A + (size_t)(bm + aRow + 64) * ldA + (k0) + aC4);                          \
    CP16(bsB + (uint32_t)((buf) * B_BYTES + bC * 48 + bH * 16),                     \
         Wh + (size_t)(bn + bC) * Kd + (k0) + bH * 8);                              \
    CPCOMMIT(); } while (0)

    float acc[2][8][4];
#pragma unroll
    for (int i = 0; i < 2; i++)
#pragma unroll
        for (int j = 0; j < 8; j++)
#pragma unroll
            for (int q = 0; q < 4; q++) acc[i][j][q] = 0.0f;

    int niter = Kd >> 4;
    GISSUE(0, 0);
    for (int it = 0; it < niter; it++) {
        const float*  Ac = As + (it & 1) * A_WORDS;
        const __half* Bc = Bs + (it & 1) * B_HALVES;
        if (it + 1 < niter) {
            GISSUE((it + 1) & 1, (it + 1) * 16);
            CPWAIT1();
        } else {
            CPWAIT0();
        }
        __syncthreads();

        uint32_t af[2][4], bf[8][2];
#pragma unroll
        for (int mt = 0; mt < 2; mt++) {
            int r = wm + mt * 16 + lr;
            float2 v0 = *(const float2*)&Ac[r * AS_STR + 2 * lc];
            float2 v1 = *(const float2*)&Ac[(r + 8) * AS_STR + 2 * lc];
            float2 v2 = *(const float2*)&Ac[r * AS_STR + 2 * lc + 8];
            float2 v3 = *(const float2*)&Ac[(r + 8) * AS_STR + 2 * lc + 8];
            af[mt][0] = packh2(v0.x, v0.y);
            af[mt][1] = packh2(v1.x, v1.y);
            af[mt][2] = packh2(v2.x, v2.y);
            af[mt][3] = packh2(v3.x, v3.y);
        }
#pragma unroll
        for (int nt = 0; nt < 8; nt++) {
            int c = wn + nt * 8 + lr;
            bf[nt][0] = *(const uint32_t*)&Bc[c * 24 + 2 * lc];
            bf[nt][1] = *(const uint32_t*)&Bc[c * 24 + 2 * lc + 8];
        }
#pragma unroll
        for (int mt = 0; mt < 2; mt++)
#pragma unroll
            for (int nt = 0; nt < 8; nt++)
                MMA_F16(acc[mt][nt][0], acc[mt][nt][1], acc[mt][nt][2], acc[mt][nt][3],
                        af[mt][0], af[mt][1], af[mt][2], af[mt][3],
                        bf[nt][0], bf[nt][1]);
        __syncthreads();
    }
#undef GISSUE

    float csum[16], csq[16];
#pragma unroll
    for (int t = 0; t < 16; t++) { csum[t] = 0.f; csq[t] = 0.f; }

#pragma unroll
    for (int mt = 0; mt < 2; mt++) {
#pragma unroll
        for (int half = 0; half < 2; half++) {
            int row = bm + wm + mt * 16 + lr + half * 8;
            size_t ro = (size_t)row * ldC;
            size_t rr = (size_t)row * Cout;
#pragma unroll
            for (int nt = 0; nt < 8; nt++) {
                int col = bn + wn + nt * 8 + lc * 2;
                float v0 = acc[mt][nt][half * 2];
                float v1 = acc[mt][nt][half * 2 + 1];
                if (bias) { v0 += bias[col]; v1 += bias[col + 1]; }
                if (res)  { v0 += res[rr + col]; v1 += res[rr + col + 1]; }
                if (accum){ v0 += C[ro + col];  v1 += C[ro + col + 1]; }
                if (relu) { v0 = fmaxf(v0, 0.f); v1 = fmaxf(v1, 0.f); }
                if (sums) {
                    csum[nt * 2]     += v0; csq[nt * 2]     = fmaf(v0, v0, csq[nt * 2]);
                    csum[nt * 2 + 1] += v1; csq[nt * 2 + 1] = fmaf(v1, v1, csq[nt * 2 + 1]);
                }
                *(float2*)&C[ro + col] = make_float2(v0, v1);
            }
        }
    }

    if (sums) {
        if (tid < 256) As[tid] = 0.f;
        __syncthreads();
#pragma unroll
        for (int t = 0; t < 16; t++) {
            int col = wn + (t >> 1) * 8 + lc * 2 + (t & 1);
            atomicAdd(&As[col], csum[t]);
            atomicAdd(&As[128 + col], csq[t]);
        }
        __syncthreads();
        if (tid < 128) {
            atomicAdd(&sums[tid],       As[tid]);
            atomicAdd(&sums[tid + 128], As[tid + 128]);
        }
    }
}

// ---------------- Chebyshev gather ----------------
__global__ void k_cheb(const float* __restrict__ Vc, const float* __restrict__ Vp,
                       float* __restrict__ Vo, const float* __restrict__ lam,
                       int mode, int ld)
{
    int gw = (blockIdx.x * blockDim.x + threadIdx.x) >> 5;
    int lane = threadIdx.x & 31;
    if (gw >= NN) return;
    float sc = 2.0f / lam[0];
    int beg = g_rowptr[gw], end = g_rowptr[gw + 1];
    float dn = g_dis[gw];
    float4 acc = make_float4(0.f, 0.f, 0.f, 0.f);
    for (int j = beg; j < end; j++) {
        int s = g_ecol[j];
        float w = dn * g_dis[s];
        float4 v = *(const float4*)&Vc[(size_t)s * ld + lane * 4];
        acc.x = fmaf(w, v.x, acc.x);
        acc.y = fmaf(w, v.y, acc.y);
        acc.z = fmaf(w, v.z, acc.z);
        acc.w = fmaf(w, v.w, acc.w);
    }
    float4 vc = *(const float4*)&Vc[(size_t)gw * ld + lane * 4];
    float sm1 = sc - 1.0f;
    float4 r;
    r.x = sm1 * vc.x - sc * acc.x;
    r.y = sm1 * vc.y - sc * acc.y;
    r.z = sm1 * vc.z - sc * acc.z;
    r.w = sm1 * vc.w - sc * acc.w;
    if (mode) {
        float4 vp = *(const float4*)&Vp[(size_t)gw * ld + lane * 4];
        r.x = 2.f * r.x - vp.x; r.y = 2.f * r.y - vp.y;
        r.z = 2.f * r.z - vp.z; r.w = 2.f * r.w - vp.w;
    }
    *(float4*)&Vo[(size_t)gw * ld + lane * 4] = r;
}

// ---------------- S = U^T @ Hp (tf32 mma, atomic accumulate) ----------------
#define US_STR 132
__global__ __launch_bounds__(256, 2) void k_utgemm_tc(const float* __restrict__ U,
                                                      const float* __restrict__ Hp)
{
    __shared__ float Us[16 * US_STR];
    __shared__ float Hs[16 * US_STR];
    int n0 = blockIdx.x * 256;
    int tid = threadIdx.x;
    int warp = tid >> 5, lane = tid & 31;
    int wm = (warp >> 1) * 32, wn = (warp & 1) * 64;
    int lr = lane >> 2, lc = lane & 3;

    float acc[2][8][4];
#pragma unroll
    for (int i = 0; i < 2; i++)
#pragma unroll
        for (int j = 0; j < 8; j++)
#pragma unroll
            for (int q = 0; q < 4; q++) acc[i][j][q] = 0.f;

    for (int nb = 0; nb < 256; nb += 16) {
#pragma unroll
        for (int l = 0; l < 2; l++) {
            int i = tid + l * 256;
            int row = i >> 5, c4 = (i & 31) * 4;
            *(float4*)&Us[row * US_STR + c4] =
                cvt_tf32_4(*(const float4*)&U [(size_t)(n0 + nb + row) * 128 + c4]);
            *(float4*)&Hs[row * US_STR + c4] =
                cvt_tf32_4(*(const float4*)&Hp[(size_t)(n0 + nb + row) * 128 + c4]);
        }
        __syncthreads();
#pragma unroll
        for (int kk = 0; kk < 16; kk += 8) {
            uint32_t af[2][4], bf[8][2];
#pragma unroll
            for (int mt = 0; mt < 2; mt++) {
                int m = wm + mt * 16 + lr;
                af[mt][0] = __float_as_uint(Us[(kk + lc) * US_STR + m]);
                af[mt][1] = __float_as_uint(Us[(kk + lc) * US_STR + m + 8]);
                af[mt][2] = __float_as_uint(Us[(kk + lc + 4) * US_STR + m]);
                af[mt][3] = __float_as_uint(Us[(kk + lc + 4) * US_STR + m + 8]);
            }
#pragma unroll
            for (int nt = 0; nt < 8; nt++) {
                int c = wn + nt * 8 + lr;
                bf[nt][0] = __float_as_uint(Hs[(kk + lc) * US_STR + c]);
                bf[nt][1] = __float_as_uint(Hs[(kk + lc + 4) * US_STR + c]);
            }
#pragma unroll
            for (int mt = 0; mt < 2; mt++)
#pragma unroll
                for (int nt = 0; nt < 8; nt++)
                    MMA_TF32(acc[mt][nt][0], acc[mt][nt][1], acc[mt][nt][2], acc[mt][nt][3],
                             af[mt][0], af[mt][1], af[mt][2], af[mt][3],
                             bf[nt][0], bf[nt][1]);
        }
        __syncthreads();
    }
#pragma unroll
    for (int mt = 0; mt < 2; mt++)
#pragma unroll
        for (int half = 0; half < 2; half++) {
            int row = wm + mt * 16 + lr + half * 8;
#pragma unroll
            for (int nt = 0; nt < 8; nt++) {
                int col = wn + nt * 8 + lc * 2;
                atomicAdd(&g_S[row * 128 + col],     acc[mt][nt][half * 2]);
                atomicAdd(&g_S[row * 128 + col + 1], acc[mt][nt][half * 2 + 1]);
            }
        }
}

// scale + TRANSPOSE + fp16: Sth[c][k] = half(S[k][c] * exp(-gamma*Lambda_k^2))
__global__ void k_scaleS(const float* __restrict__ Lambda, const float* __restrict__ gamma) {
    int i = blockIdx.x * blockDim.x + threadIdx.x;
    if (i < KEIG * CC) {
        int c = i >> 7, k = i & 127;
        float l = Lambda[k];
        g_Sth[i] = __float2half(g_S[k * 128 + c] * expf(-gamma[0] * l * l));
    }
}

// ---------------- BN finalize / elementwise ----------------
__global__ void k_bnfin(const float* __restrict__ sum, const float* __restrict__ sq,
                        const float* __restrict__ w, const float* __restrict__ b,
                        float* __restrict__ a, float* __restrict__ bs)
{
    int c = threadIdx.x;
    float mu  = sum[c] * (1.0f / NN);
    float var = sq[c]  * (1.0f / NN) - mu * mu;
    float aa = w[c] * rsqrtf(var + BN_EPS);
    a[c]  = aa;
    bs[c] = b[c] - mu * aa;
}

__global__ void k_combine(const float* __restrict__ pre, const float* __restrict__ h2,
                          float* __restrict__ out0)
{
    int i = blockIdx.x * blockDim.x + threadIdx.x;
    int col4 = (i & 31) * 4;
    float4 p = ((const float4*)pre)[i];
    float4 q = ((const float4*)h2)[i];
    float4 a1 = *(const float4*)&g_ab[col4];
    float4 b1 = *(const float4*)&g_ab[128 + col4];
    float4 a2 = *(const float4*)&g_ab[256 + col4];
    float4 b2 = *(const float4*)&g_ab[384 + col4];
    float4 rv;
    rv.x = fmaf(p.x, a1.x, b1.x) + fmaf(q.x, a2.x, b2.x);
    rv.y = fmaf(p.y, a1.y, b1.y) + fmaf(q.y, a2.y, b2.y);
    rv.z = fmaf(p.z, a1.z, b1.z) + fmaf(q.z, a2.z, b2.z);
    rv.w = fmaf(p.w, a1.w, b1.w) + fmaf(q.w, a2.w, b2.w);
    ((float4*)out0)[i] = rv;
}

__global__ void k_final(const float* __restrict__ X, float* __restrict__ out) {
    int i = blockIdx.x * blockDim.x + threadIdx.x;
    int col4 = (i & 31) * 4;
    float4 v = ((const float4*)X)[i];
    float4 a3 = *(const float4*)&g_ab[512 + col4];
    float4 b3 = *(const float4*)&g_ab[640 + col4];
    float4 rv;
    rv.x = fmaf(v.x, a3.x, b3.x); rv.y = fmaf(v.y, a3.y, b3.y);
    rv.z = fmaf(v.z, a3.z, b3.z); rv.w = fmaf(v.w, a3.w, b3.w);
    ((float4*)out)[i] = rv;
}

// ---------------- fused flash attention (tf32 mma) ----------------
#define KV_STR 36
__global__ __launch_bounds__(256, 2) void k_flash(const float* __restrict__ qkv,
                                                  float* __restrict__ out)
{
    __shared__ float Ks[128 * KV_STR];
    __shared__ float Vs[128 * KV_STR];
    int bh = blockIdx.y;
    int b = bh >> 2, h = bh & 3;
    int i0 = blockIdx.x * 128;
    int tid = threadIdx.x;
    int warp = tid >> 5, lane = tid & 31;
    int lr = lane >> 2, lc = lane & 3;
    const unsigned FULL = 0xffffffffu;
    const float scl = 0.17677669529663687f;

    const float* qb = qkv + (size_t)(b * NGR + i0 + warp * 16) * 384 + h * DH;
    uint32_t qf[4][4];
#pragma unroll
    for (int kc = 0; kc < 4; kc++) {
        qf[kc][0] = __float_as_uint(cvt_tf32(qb[(size_t)lr * 384 + kc * 8 + lc]));
        qf[kc][1] = __float_as_uint(cvt_tf32(qb[(size_t)(lr + 8) * 384 + kc * 8 + lc]));
        qf[kc][2] = __float_as_uint(cvt_tf32(qb[(size_t)lr * 384 + kc * 8 + lc + 4]));
        qf[kc][3] = __float_as_uint(cvt_tf32(qb[(size_t)(lr + 8) * 384 + kc * 8 + lc + 4]));
    }

    float m0 = -1e30f, m1 = -1e30f, l0 = 0.f, l1 = 0.f;
    float o[4][4];
#pragma unroll
    for (int nt = 0; nt < 4; nt++)
#pragma unroll
        for (int q = 0; q < 4; q++) o[nt][q] = 0.f;

    int lsrcA = (lane & ~3) | (lc >> 1);
    int lsrcB = lsrcA + 2;
    bool odd = (lc & 1);

    for (int j0 = 0; j0 < NGR; j0 += 128) {
        __syncthreads();
        const float* kb = qkv + (size_t)(b * NGR + j0) * 384 + 128 + h * DH;
        const float* vb = qkv + (size_t)(b * NGR + j0) * 384 + 256 + h * DH;
#pragma unroll
        for (int l4 = 0; l4 < 4; l4++) {
            int i = tid + l4 * 256;
            int row = i >> 3, c4 = (i & 7) * 4;
            *(float4*)&Ks[row * KV_STR + c4] =
                cvt_tf32_4(*(const float4*)&kb[(size_t)row * 384 + c4]);
            *(float4*)&Vs[row * KV_STR + c4] =
                cvt_tf32_4(*(const float4*)&vb[(size_t)row * 384 + c4]);
        }
        __syncthreads();

        float s[16][4];
#pragma unroll
        for (int g = 0; g < 16; g++)
#pragma unroll
            for (int q = 0; q < 4; q++) s[g][q] = 0.f;
#pragma unroll
        for (int kc = 0; kc < 4; kc++) {
#pragma unroll
            for (int g = 0; g < 16; g++) {
                int c = g * 8 + lr;
                uint32_t b0 = __float_as_uint(Ks[c * KV_STR + kc * 8 + lc]);
                uint32_t b1 = __float_as_uint(Ks[c * KV_STR + kc * 8 + lc + 4]);
                MMA_TF32(s[g][0], s[g][1], s[g][2], s[g][3],
                         qf[kc][0], qf[kc][1], qf[kc][2], qf[kc][3], b0, b1);
            }
        }

        float mn0 = m0, mn1 = m1;
#pragma unroll
        for (int g = 0; g < 16; g++) {
            s[g][0] *= scl; s[g][1] *= scl; s[g][2] *= scl; s[g][3] *= scl;
            mn0 = fmaxf(mn0, fmaxf(s[g][0], s[g][1]));
            mn1 = fmaxf(mn1, fmaxf(s[g][2], s[g][3]));
        }
        mn0 = fmaxf(mn0, __shfl_xor_sync(FULL, mn0, 1));
        mn0 = fmaxf(mn0, __shfl_xor_sync(FULL, mn0, 2));
        mn1 = fmaxf(mn1, __shfl_xor_sync(FULL, mn1, 1));
        mn1 = fmaxf(mn1, __shfl_xor_sync(FULL, mn1, 2));
        float al0 = __expf(m0 - mn0);
        float al1 = __expf(m1 - mn1);
        m0 = mn0; m1 = mn1;
        float rs0 = 0.f, rs1 = 0.f;
#pragma unroll
        for (int g = 0; g < 16; g++) {
            s[g][0] = __expf(s[g][0] - mn0);
            s[g][1] = __expf(s[g][1] - mn0);
            s[g][2] = __expf(s[g][2] - mn1);
            s[g][3] = __expf(s[g][3] - mn1);
            rs0 += s[g][0] + s[g][1];
            rs1 += s[g][2] + s[g][3];
            s[g][0] = cvt_tf32(s[g][0]); s[g][1] = cvt_tf32(s[g][1]);
            s[g][2] = cvt_tf32(s[g][2]); s[g][3] = cvt_tf32(s[g][3]);
        }
        rs0 += __shfl_xor_sync(FULL, rs0, 1);
        rs0 += __shfl_xor_sync(FULL, rs0, 2);
        rs1 += __shfl_xor_sync(FULL, rs1, 1);
        rs1 += __shfl_xor_sync(FULL, rs1, 2);
        l0 = l0 * al0 + rs0;
        l1 = l1 * al1 + rs1;
#pragma unroll
        for (int nt = 0; nt < 4; nt++) {
            o[nt][0] *= al0; o[nt][1] *= al0;
            o[nt][2] *= al1; o[nt][3] *= al1;
        }

#pragma unroll
        for (int g = 0; g < 16; g++) {
            float t0A = __shfl_sync(FULL, s[g][0], lsrcA);
            float t1A = __shfl_sync(FULL, s[g][1], lsrcA);
            float t2A = __shfl_sync(FULL, s[g][2], lsrcA);
            float t3A = __shfl_sync(FULL, s[g][3], lsrcA);
            float t0B = __shfl_sync(FULL, s[g][0], lsrcB);
            float t1B = __shfl_sync(FULL, s[g][1], lsrcB);
            float t2B = __shfl_sync(FULL, s[g][2], lsrcB);
            float t3B = __shfl_sync(FULL, s[g][3], lsrcB);
            uint32_t a0 = __float_as_uint(odd ? t1A : t0A);
            uint32_t a1 = __float_as_uint(odd ? t3A : t2A);
            uint32_t a2 = __float_as_uint(odd ? t1B : t0B);
            uint32_t a3 = __float_as_uint(odd ? t3B : t2B);
#pragma unroll
            for (int nt = 0; nt < 4; nt++) {
                uint32_t b0 = __float_as_uint(Vs[(g * 8 + lc) * KV_STR + nt * 8 + lr]);
                uint32_t b1 = __float_as_uint(Vs[(g * 8 + lc + 4) * KV_STR + nt * 8 + lr]);
                MMA_TF32(o[nt][0], o[nt][1], o[nt][2], o[nt][3],
                         a0, a1, a2, a3, b0, b1);
            }
        }
    }

    float inv0 = 1.0f / l0, inv1 = 1.0f / l1;
    int row0 = b * NGR + i0 + warp * 16 + lr;
#pragma unroll
    for (int nt = 0; nt < 4; nt++) {
        int col = h * DH + nt * 8 + lc * 2;
        *(float2*)&out[(size_t)row0 * CC + col] =
            make_float2(o[nt][0] * inv0, o[nt][1] * inv0);
        *(float2*)&out[(size_t)(row0 + 8) * CC + col] =
            make_float2(o[nt][2] * inv1, o[nt][3] * inv1);
    }
}

// ---------------- host ----------------
static float* symf(const void* p) { return (float*)p; }

extern "C" void kernel_launch(void* const* d_in, const int* in_sizes, int n_in,
                              void* d_out, int out_size)
{
    const float* x      = (const float*)d_in[0];
    const float* U      = (const float*)d_in[1];
    const float* Lambda = (const float*)d_in[2];
    const float* lamMax = (const float*)d_in[3];
    const float* w_spa1 = (const float*)d_in[4];  const float* b_spa1 = (const float*)d_in[5];
    const float* w_spa2 = (const float*)d_in[6];  const float* b_spa2 = (const float*)d_in[7];
    const float* w_spe1 = (const float*)d_in[8];  const float* b_spe1 = (const float*)d_in[9];
    const float* w_spe2 = (const float*)d_in[10]; const float* b_spe2 = (const float*)d_in[11];
    const float* cheb_w = (const float*)d_in[12]; const float* cheb_b = (const float*)d_in[13];
    const float* gamma  = (const float*)d_in[14]; const float* w_proj = (const float*)d_in[15];
    const float* w_qkv  = (const float*)d_in[16]; const float* b_qkv  = (const float*)d_in[17];
    const float* w_out  = (const float*)d_in[18]; const float* b_out  = (const float*)d_in[19];
    const float* mlp_w1 = (const float*)d_in[20]; const float* mlp_b1 = (const float*)d_in[21];
    const float* mlp_w2 = (const float*)d_in[22]; const float* mlp_b2 = (const float*)d_in[23];
    const float* bn1w = (const float*)d_in[24]; const float* bn1b = (const float*)d_in[25];
    const float* bn2w = (const float*)d_in[26]; const float* bn2b = (const float*)d_in[27];
    const float* bn3w = (const float*)d_in[28]; const float* bn3b = (const float*)d_in[29];
    const int*   ei   = (const int*)d_in[30];
    const int* src = ei;
    const int* dst = ei + EE;
    float* out = (float*)d_out;

    void *pBIG, *pHID, *pLOC, *pXSP, *pHPJ, *pATT, *pH2, *pQKV, *pS, *pSth,
         *pOUTD, *pIND, *pSUMS, *pAB, *pWRD;
    cudaGetSymbolAddress(&pBIG, g_big);   cudaGetSymbolAddress(&pHID, g_hid);
    cudaGetSymbolAddress(&pLOC, g_loc);   cudaGetSymbolAddress(&pXSP, g_xspec);
    cudaGetSymbolAddress(&pHPJ, g_hproj); cudaGetSymbolAddress(&pATT, g_att);
    cudaGetSymbolAddress(&pH2, g_h2);     cudaGetSymbolAddress(&pQKV, g_qkv);
    cudaGetSymbolAddress(&pS, g_S);       cudaGetSymbolAddress(&pSth, g_Sth);
    cudaGetSymbolAddress(&pOUTD, g_outdeg); cudaGetSymbolAddress(&pIND, g_indeg);
    cudaGetSymbolAddress(&pSUMS, g_sums);   cudaGetSymbolAddress(&pAB, g_ab);
    cudaGetSymbolAddress(&pWRD, g_wrd);

    float* BIG = symf(pBIG); float* HID = symf(pHID); float* LOC = symf(pLOC);
    float* XSP = symf(pXSP); float* HPJ = symf(pHPJ); float* ATT = symf(pATT);
    float* H2  = symf(pH2);  float* QKV = symf(pQKV); float* SUMS = symf(pSUMS);
    __half* WR = (__half*)pWRD;
    float* HIDa = HID;
    float* HIDb = HID + (size_t)NN * CC;

    static cudaStream_t s2 = 0, s3 = 0;
    static cudaEvent_t evF = 0, evB = 0, evC = 0;
    if (!s2) {
        cudaStreamCreateWithFlags(&s2, cudaStreamNonBlocking);
        cudaStreamCreateWithFlags(&s3, cudaStreamNonBlocking);
        cudaEventCreateWithFlags(&evF, cudaEventDisableTiming);
        cudaEventCreateWithFlags(&evB, cudaEventDisableTiming);
        cudaEventCreateWithFlags(&evC, cudaEventDisableTiming);
    }

    cudaMemsetAsync(pOUTD, 0, NN * sizeof(int));
    cudaMemsetAsync(pIND,  0, NN * sizeof(int));
    cudaMemsetAsync(pS,    0, KEIG * CC * sizeof(float));
    cudaMemsetAsync(pSUMS, 0, 6 * CC * sizeof(float));

    auto TRW = [&](const float* in, __half* outw, int K, int C) {
        k_trw<<<(K * C + 255) / 256, 256>>>(in, outw, K, C);
    };
    TRW(w_spa1, WR + OSPA1, 128, 128);
    TRW(w_spa2, WR + OSPA2, 128, 128);
    TRW(w_spe1, WR + OSPE1, 128, 128);
    TRW(w_spe2, WR + OSPE2, 128, 128);
    TRW(w_proj, WR + OPROJ, 128, 128);
    TRW(cheb_w, WR + OCHEB, 640, 128);
    TRW(w_qkv,  WR + OQKV,  128, 384);
    TRW(w_out,  WR + OWOUT, 128, 128);
    TRW(mlp_w1, WR + OMLP1, 128, 256);
    TRW(mlp_w2, WR + OMLP2, 256, 128);

    cudaEventRecord(evF, 0);
    cudaStreamWaitEvent(s2, evF, 0);
    cudaStreamWaitEvent(s3, evF, 0);

    auto GEMM = [&](cudaStream_t st, const float* A, const __half* Wh, const float* bias,
                    const float* res, float* C, int M, int Kd, int ldA, int Cout, int ldC,
                    int relu, int accum, float* sums) {
        dim3 g(M / 128, Cout / 128);
        k_gemm<<<g, 256, 0, st>>>(A, Wh, bias, res, C, M, Kd, ldA, Cout, ldC, relu, accum, sums);
    };

    // ---- branch A (stream 0): spatial MLP + prep + Chebyshev ----
    GEMM(0, x, WR + OSPA1, b_spa1, nullptr, HIDa, NN, 128, 128, 128, 128, 1, 0, nullptr);
    GEMM(0, HIDa, WR + OSPA2, b_spa2, nullptr, BIG, NN, 128, 128, 128, 640, 0, 0, nullptr);
    k_count<<<EE / 256, 256>>>(src, dst);
    k_dis<<<NN / 256, 256>>>();
    k_scan1<<<128, 256>>>();
    k_scan2<<<1, 128>>>();
    k_scan3<<<128, 256>>>();
    k_fill<<<EE / 256, 256>>>(src, dst);
    k_cheb<<<NN / 8, 256>>>(BIG, nullptr, BIG + 128, lamMax, 0, 640);
    for (int k = 2; k < KCH; k++)
        k_cheb<<<NN / 8, 256>>>(BIG + (k - 1) * 128, BIG + (k - 2) * 128,
                                BIG + k * 128, lamMax, 1, 640);
    GEMM(0, BIG, WR + OCHEB, nullptr, nullptr, LOC, NN, 640, 640, 128, 128, 0, 0, nullptr);

    // ---- branch B (s2): spectral ----
    GEMM(s2, x, WR + OSPE1, b_spe1, nullptr, HIDb, NN, 128, 128, 128, 128, 1, 0, nullptr);
    GEMM(s2, HIDb, WR + OSPE2, b_spe2, nullptr, XSP, NN, 128, 128, 128, 128, 0, 0, nullptr);
    GEMM(s2, XSP, WR + OPROJ, nullptr, nullptr, HPJ, NN, 128, 128, 128, 128, 0, 0, nullptr);
    k_utgemm_tc<<<NN / 256, 256, 0, s2>>>(U, HPJ);
    k_scaleS<<<(KEIG * CC) / 256, 256, 0, s2>>>(Lambda, gamma);
    cudaEventRecord(evB, s2);

    // ---- branch C (s3): attention ----
    GEMM(s3, x, WR + OQKV, b_qkv, nullptr, QKV, NN, 128, 128, 384, 384, 0, 0, nullptr);
    {
        dim3 gf(NGR / 128, BBG * HH);
        k_flash<<<gf, 256, 0, s3>>>(QKV, ATT);
    }
    GEMM(s3, ATT, WR + OWOUT, b_out, x, H2, NN, 128, 128, 128, 128, 0, 0, SUMS + 256);
    cudaEventRecord(evC, s3);

    // ---- join on stream 0 ----
    cudaStreamWaitEvent(0, evB, 0);
    GEMM(0, U, (__half*)pSth, cheb_b, x, LOC, NN, 128, 128, 128, 128, 0, 1, SUMS);
    cudaStreamWaitEvent(0, evC, 0);

    k_bnfin<<<1, 128>>>(SUMS,       SUMS + 128, bn1w, bn1b, symf(pAB),       symf(pAB) + 128);
    k_bnfin<<<1, 128>>>(SUMS + 256, SUMS + 384, bn2w, bn2b, symf(pAB) + 256, symf(pAB) + 384);
    k_combine<<<(NN * CC / 4) / 256, 256>>>(LOC, H2, XSP);

    // ---- final MLP with residual (fused BN3 stats) ----
    GEMM(0, XSP, WR + OMLP1, mlp_b1, nullptr, HID, NN, 128, 128, 256, 256, 1, 0, nullptr);
    GEMM(0, HID, WR + OMLP2, mlp_b2, XSP, LOC, NN, 256, 256, 128, 128, 0, 0, SUMS + 512);

    k_bnfin<<<1, 128>>>(SUMS + 512, SUMS + 640, bn3w, bn3b, symf(pAB) + 512, symf(pAB) + 640);
    k_final<<<(NN * CC / 4) / 256, 256>>>(LOC, out);
}

// round 12
// speedup vs baseline: 1.0469x; 1.0469x over previous
#include <cuda_runtime.h>
#include <cuda_fp16.h>
#include <math.h>
#include <stdint.h>

#define NN   32768
#define CC   128
#define EE   524288
#define BBG  64
#define NGR  512
#define HH   4
#define DH   32
#define KEIG 128
#define KCH  5
#define BN_EPS 1e-5f

// ---------------- static scratch ----------------
__device__ float g_big [NN * 640];
__device__ float g_hid [NN * 2 * CC];
__device__ float g_loc [NN * CC];
__device__ float g_xspec[NN * CC];
__device__ float g_hproj[NN * CC];
__device__ float g_att [NN * CC];
__device__ float g_h2  [NN * CC];
__device__ float g_qkv [NN * 3 * CC];
__device__ float g_S   [KEIG * CC];
__device__ __half g_Sth[KEIG * CC];
__device__ float g_dis [NN];
__device__ int   g_outdeg[NN];
__device__ int   g_indeg [NN];
__device__ int   g_rowptr[NN + 1];
__device__ int   g_cursor[NN];
__device__ int   g_ecol  [EE];
__device__ int   g_blksum[128];
__device__ int   g_blkoff[128];
__device__ float g_sums[6 * CC];
__device__ float g_ab  [6 * CC];

// fp16 TRANSPOSED weights: layout [Cout][Kd]
#define OSPA1 0
#define OSPA2 16384
#define OSPE1 32768
#define OSPE2 49152
#define OPROJ 65536
#define OCHEB 81920
#define OQKV  163840
#define OWOUT 212992
#define OMLP1 229376
#define OMLP2 262144
#define WTOT  294912
__device__ __half g_wrd[WTOT];

__device__ __forceinline__ float cvt_tf32(float x) {
    float r;
    asm("cvt.rna.tf32.f32 %0, %1;" : "=f"(r) : "f"(x));
    return r;
}
__device__ __forceinline__ float4 cvt_tf32_4(float4 v) {
    v.x = cvt_tf32(v.x); v.y = cvt_tf32(v.y);
    v.z = cvt_tf32(v.z); v.w = cvt_tf32(v.w);
    return v;
}
#define MMA_TF32(d0,d1,d2,d3,a0,a1,a2,a3,b0,b1)                               \
    asm volatile("mma.sync.aligned.m16n8k8.row.col.f32.tf32.tf32.f32 "        \
        "{%0,%1,%2,%3}, {%4,%5,%6,%7}, {%8,%9}, {%0,%1,%2,%3};"               \
        : "+f"(d0), "+f"(d1), "+f"(d2), "+f"(d3)                              \
        : "r"(a0), "r"(a1), "r"(a2), "r"(a3), "r"(b0), "r"(b1))

#define MMA_F16(d0,d1,d2,d3,a0,a1,a2,a3,b0,b1)                                \
    asm volatile("mma.sync.aligned.m16n8k16.row.col.f32.f16.f16.f32 "         \
        "{%0,%1,%2,%3}, {%4,%5,%6,%7}, {%8,%9}, {%0,%1,%2,%3};"               \
        : "+f"(d0), "+f"(d1), "+f"(d2), "+f"(d3)                              \
        : "r"(a0), "r"(a1), "r"(a2), "r"(a3), "r"(b0), "r"(b1))

__device__ __forceinline__ uint32_t packh2(float lo, float hi) {
    __half2 h = __floats2half2_rn(lo, hi);
    return *(uint32_t*)&h;
}

#define CP16(dst32, srcp) \
    asm volatile("cp.async.cg.shared.global [%0], [%1], 16;" :: "r"(dst32), "l"(srcp))
#define CPCOMMIT() asm volatile("cp.async.commit_group;")
#define CPWAIT0()  asm volatile("cp.async.wait_group 0;")
#define CPWAIT1()  asm volatile("cp.async.wait_group 1;")

// ---------------- fused weight transpose+convert (ALL weights, one launch) ----
// out[seg][c*K+k] = half(in[seg][k*C+c])
__global__ void k_trwAll(const float* __restrict__ w0, const float* __restrict__ w1,
                         const float* __restrict__ w2, const float* __restrict__ w3,
                         const float* __restrict__ w4, const float* __restrict__ w5,
                         const float* __restrict__ w6, const float* __restrict__ w7,
                         const float* __restrict__ w8, const float* __restrict__ w9)
{
    int i = blockIdx.x * 256 + threadIdx.x;
    if (i >= WTOT) return;
    const float* src; int off, K, C;
    if      (i < OSPA2) { src = w0; off = OSPA1; K = 128; C = 128; }
    else if (i < OSPE1) { src = w1; off = OSPA2; K = 128; C = 128; }
    else if (i < OSPE2) { src = w2; off = OSPE1; K = 128; C = 128; }
    else if (i < OPROJ) { src = w3; off = OSPE2; K = 128; C = 128; }
    else if (i < OCHEB) { src = w4; off = OPROJ; K = 128; C = 128; }
    else if (i < OQKV)  { src = w5; off = OCHEB; K = 640; C = 128; }
    else if (i < OWOUT) { src = w6; off = OQKV;  K = 128; C = 384; }
    else if (i < OMLP1) { src = w7; off = OWOUT; K = 128; C = 128; }
    else if (i < OMLP2) { src = w8; off = OMLP1; K = 128; C = 256; }
    else                { src = w9; off = OMLP2; K = 256; C = 128; }
    int o = i - off;
    int c = o / K, k = o - c * K;
    g_wrd[i] = __float2half(src[k * C + c]);
}

// ---------------- graph preprocessing ----------------
__global__ void k_count(const int* __restrict__ src, const int* __restrict__ dst) {
    int e = blockIdx.x * blockDim.x + threadIdx.x;
    if (e < EE) {
        atomicAdd(&g_outdeg[src[e]], 1);
        atomicAdd(&g_indeg [dst[e]], 1);
    }
}

__global__ void k_dis() {
    int n = blockIdx.x * blockDim.x + threadIdx.x;
    if (n < NN) {
        int d = g_outdeg[n];
        g_dis[n] = (d > 0) ? rsqrtf((float)d) : 0.0f;
    }
}

__global__ void k_scan1() {
    __shared__ int sh[256];
    int t = threadIdx.x;
    int i = blockIdx.x * 256 + t;
    int v = g_indeg[i];
    sh[t] = v;
    __syncthreads();
#pragma unroll
    for (int off = 1; off < 256; off <<= 1) {
        int u = (t >= off) ? sh[t - off] : 0;
        __syncthreads();
        sh[t] += u;
        __syncthreads();
    }
    g_rowptr[i] = sh[t] - v;
    if (t == 255) g_blksum[blockIdx.x] = sh[255];
}

__global__ void k_scan2() {
    __shared__ int sh[128];
    int t = threadIdx.x;
    int v = g_blksum[t];
    sh[t] = v;
    __syncthreads();
#pragma unroll
    for (int off = 1; off < 128; off <<= 1) {
        int u = (t >= off) ? sh[t - off] : 0;
        __syncthreads();
        sh[t] += u;
        __syncthreads();
    }
    g_blkoff[t] = sh[t] - v;
    if (t == 127) g_rowptr[NN] = sh[127];
}

__global__ void k_scan3() {
    int t = threadIdx.x;
    int i = blockIdx.x * 256 + t;
    int r = g_rowptr[i] + g_blkoff[blockIdx.x];
    g_rowptr[i] = r;
    g_cursor[i] = r;
}

__global__ void k_fill(const int* __restrict__ src, const int* __restrict__ dst) {
    int e = blockIdx.x * blockDim.x + threadIdx.x;
    if (e < EE) {
        int p = atomicAdd(&g_cursor[dst[e]], 1);
        g_ecol[p] = src[e];
    }
}

// ---------------- fp16 GEMM, cp.async double-buffered, 2 CTAs/SM -------------
#define AS_STR 20
#define A_WORDS (128 * AS_STR)
#define B_HALVES (128 * 24)
#define B_BYTES  (B_HALVES * 2)
__global__ __launch_bounds__(256, 2) void k_gemm(
    const float* __restrict__ A, const __half* __restrict__ Wh,
    const float* __restrict__ bias, const float* __restrict__ res,
    float* __restrict__ C, int M, int Kd, int ldA, int Cout, int ldC,
    int relu, int accum, float* __restrict__ sums)
{
    __shared__ float  As[2 * A_WORDS];
    __shared__ __half Bs[2 * B_HALVES];
    int bm = blockIdx.x * 128;
    int bn = blockIdx.y * 128;
    int tid = threadIdx.x;
    int warp = tid >> 5, lane = tid & 31;
    int wm = (warp >> 1) * 32;
    int wn = (warp & 1) * 64;
    int lr = lane >> 2;
    int lc = lane & 3;

    uint32_t asB = (uint32_t)__cvta_generic_to_shared(As);
    uint32_t bsB = (uint32_t)__cvta_generic_to_shared(Bs);
    int aRow = tid >> 2, aC4 = (tid & 3) * 4;
    int bC = tid >> 1, bH = tid & 1;

#define GISSUE(buf, k0) do {                                                        \
    CP16(asB + (uint32_t)((buf) * A_WORDS + aRow * AS_STR + aC4) * 4u,              \
         A + (size_t)(bm + aRow) * ldA + (k0) + aC4);                               \
    CP16(asB + (uint32_t)((buf) * A_WORDS + (aRow + 64) * AS_STR + aC4) * 4u,       \
         A + (size_t)(bm + aRow + 64) * ldA + (k0) + aC4);                          \
    CP16(bsB + (uint32_t)((buf) * B_BYTES + bC * 48 + bH * 16),                     \
         Wh + (size_t)(bn + bC) * Kd + (k0) + bH * 8);                              \
    CPCOMMIT(); } while (0)

    float acc[2][8][4];
#pragma unroll
    for (int i = 0; i < 2; i++)
#pragma unroll
        for (int j = 0; j < 8; j++)
#pragma unroll
            for (int q = 0; q < 4; q++) acc[i][j][q] = 0.0f;

    int niter = Kd >> 4;
    GISSUE(0, 0);
    for (int it = 0; it < niter; it++) {
        const float*  Ac = As + (it & 1) * A_WORDS;
        const __half* Bc = Bs + (it & 1) * B_HALVES;
        if (it + 1 < niter) {
            GISSUE((it + 1) & 1, (it + 1) * 16);
            CPWAIT1();
        } else {
            CPWAIT0();
        }
        __syncthreads();

        uint32_t af[2][4], bf[8][2];
#pragma unroll
        for (int mt = 0; mt < 2; mt++) {
            int r = wm + mt * 16 + lr;
            float2 v0 = *(const float2*)&Ac[r * AS_STR + 2 * lc];
            float2 v1 = *(const float2*)&Ac[(r + 8) * AS_STR + 2 * lc];
            float2 v2 = *(const float2*)&Ac[r * AS_STR + 2 * lc + 8];
            float2 v3 = *(const float2*)&Ac[(r + 8) * AS_STR + 2 * lc + 8];
            af[mt][0] = packh2(v0.x, v0.y);
            af[mt][1] = packh2(v1.x, v1.y);
            af[mt][2] = packh2(v2.x, v2.y);
            af[mt][3] = packh2(v3.x, v3.y);
        }
#pragma unroll
        for (int nt = 0; nt < 8; nt++) {
            int c = wn + nt * 8 + lr;
            bf[nt][0] = *(const uint32_t*)&Bc[c * 24 + 2 * lc];
            bf[nt][1] = *(const uint32_t*)&Bc[c * 24 + 2 * lc + 8];
        }
#pragma unroll
        for (int mt = 0; mt < 2; mt++)
#pragma unroll
            for (int nt = 0; nt < 8; nt++)
                MMA_F16(acc[mt][nt][0], acc[mt][nt][1], acc[mt][nt][2], acc[mt][nt][3],
                        af[mt][0], af[mt][1], af[mt][2], af[mt][3],
                        bf[nt][0], bf[nt][1]);
        __syncthreads();
    }
#undef GISSUE

    float csum[16], csq[16];
#pragma unroll
    for (int t = 0; t < 16; t++) { csum[t] = 0.f; csq[t] = 0.f; }

#pragma unroll
    for (int mt = 0; mt < 2; mt++) {
#pragma unroll
        for (int half = 0; half < 2; half++) {
            int row = bm + wm + mt * 16 + lr + half * 8;
            size_t ro = (size_t)row * ldC;
            size_t rr = (size_t)row * Cout;
#pragma unroll
            for (int nt = 0; nt < 8; nt++) {
                int col = bn + wn + nt * 8 + lc * 2;
                float v0 = acc[mt][nt][half * 2];
                float v1 = acc[mt][nt][half * 2 + 1];
                if (bias) { v0 += bias[col]; v1 += bias[col + 1]; }
                if (res)  { v0 += res[rr + col]; v1 += res[rr + col + 1]; }
                if (accum){ v0 += C[ro + col];  v1 += C[ro + col + 1]; }
                if (relu) { v0 = fmaxf(v0, 0.f); v1 = fmaxf(v1, 0.f); }
                if (sums) {
                    csum[nt * 2]     += v0; csq[nt * 2]     = fmaf(v0, v0, csq[nt * 2]);
                    csum[nt * 2 + 1] += v1; csq[nt * 2 + 1] = fmaf(v1, v1, csq[nt * 2 + 1]);
                }
                *(float2*)&C[ro + col] = make_float2(v0, v1);
            }
        }
    }

    if (sums) {
        if (tid < 256) As[tid] = 0.f;
        __syncthreads();
#pragma unroll
        for (int t = 0; t < 16; t++) {
            int col = wn + (t >> 1) * 8 + lc * 2 + (t & 1);
            atomicAdd(&As[col], csum[t]);
            atomicAdd(&As[128 + col], csq[t]);
        }
        __syncthreads();
        if (tid < 128) {
            atomicAdd(&sums[tid],       As[tid]);
            atomicAdd(&sums[tid + 128], As[tid + 128]);
        }
    }
}

// ---------------- Chebyshev gather ----------------
__global__ void k_cheb(const float* __restrict__ Vc, const float* __restrict__ Vp,
                       float* __restrict__ Vo, const float* __restrict__ lam,
                       int mode, int ld)
{
    int gw = (blockIdx.x * blockDim.x + threadIdx.x) >> 5;
    int lane = threadIdx.x & 31;
    if (gw >= NN) return;
    float sc = 2.0f / lam[0];
    int beg = g_rowptr[gw], end = g_rowptr[gw + 1];
    float dn = g_dis[gw];
    float4 acc = make_float4(0.f, 0.f, 0.f, 0.f);
    for (int j = beg; j < end; j++) {
        int s = g_ecol[j];
        float w = dn * g_dis[s];
        float4 v = *(const float4*)&Vc[(size_t)s * ld + lane * 4];
        acc.x = fmaf(w, v.x, acc.x);
        acc.y = fmaf(w, v.y, acc.y);
        acc.z = fmaf(w, v.z, acc.z);
        acc.w = fmaf(w, v.w, acc.w);
    }
    float4 vc = *(const float4*)&Vc[(size_t)gw * ld + lane * 4];
    float sm1 = sc - 1.0f;
    float4 r;
    r.x = sm1 * vc.x - sc * acc.x;
    r.y = sm1 * vc.y - sc * acc.y;
    r.z = sm1 * vc.z - sc * acc.z;
    r.w = sm1 * vc.w - sc * acc.w;
    if (mode) {
        float4 vp = *(const float4*)&Vp[(size_t)gw * ld + lane * 4];
        r.x = 2.f * r.x - vp.x; r.y = 2.f * r.y - vp.y;
        r.z = 2.f * r.z - vp.z; r.w = 2.f * r.w - vp.w;
    }
    *(float4*)&Vo[(size_t)gw * ld + lane * 4] = r;
}

// ---------------- S = U^T @ Hp (tf32 mma, atomic accumulate) ----------------
#define US_STR 132
__global__ __launch_bounds__(256, 2) void k_utgemm_tc(const float* __restrict__ U,
                                                      const float* __restrict__ Hp)
{
    __shared__ float Us[16 * US_STR];
    __shared__ float Hs[16 * US_STR];
    int n0 = blockIdx.x * 256;
    int tid = threadIdx.x;
    int warp = tid >> 5, lane = tid & 31;
    int wm = (warp >> 1) * 32, wn = (warp & 1) * 64;
    int lr = lane >> 2, lc = lane & 3;

    float acc[2][8][4];
#pragma unroll
    for (int i = 0; i < 2; i++)
#pragma unroll
        for (int j = 0; j < 8; j++)
#pragma unroll
            for (int q = 0; q < 4; q++) acc[i][j][q] = 0.f;

    for (int nb = 0; nb < 256; nb += 16) {
#pragma unroll
        for (int l = 0; l < 2; l++) {
            int i = tid + l * 256;
            int row = i >> 5, c4 = (i & 31) * 4;
            *(float4*)&Us[row * US_STR + c4] =
                cvt_tf32_4(*(const float4*)&U [(size_t)(n0 + nb + row) * 128 + c4]);
            *(float4*)&Hs[row * US_STR + c4] =
                cvt_tf32_4(*(const float4*)&Hp[(size_t)(n0 + nb + row) * 128 + c4]);
        }
        __syncthreads();
#pragma unroll
        for (int kk = 0; kk < 16; kk += 8) {
            uint32_t af[2][4], bf[8][2];
#pragma unroll
            for (int mt = 0; mt < 2; mt++) {
                int m = wm + mt * 16 + lr;
                af[mt][0] = __float_as_uint(Us[(kk + lc) * US_STR + m]);
                af[mt][1] = __float_as_uint(Us[(kk + lc) * US_STR + m + 8]);
                af[mt][2] = __float_as_uint(Us[(kk + lc + 4) * US_STR + m]);
                af[mt][3] = __float_as_uint(Us[(kk + lc + 4) * US_STR + m + 8]);
            }
#pragma unroll
            for (int nt = 0; nt < 8; nt++) {
                int c = wn + nt * 8 + lr;
                bf[nt][0] = __float_as_uint(Hs[(kk + lc) * US_STR + c]);
                bf[nt][1] = __float_as_uint(Hs[(kk + lc + 4) * US_STR + c]);
            }
#pragma unroll
            for (int mt = 0; mt < 2; mt++)
#pragma unroll
                for (int nt = 0; nt < 8; nt++)
                    MMA_TF32(acc[mt][nt][0], acc[mt][nt][1], acc[mt][nt][2], acc[mt][nt][3],
                             af[mt][0], af[mt][1], af[mt][2], af[mt][3],
                             bf[nt][0], bf[nt][1]);
        }
        __syncthreads();
    }
#pragma unroll
    for (int mt = 0; mt < 2; mt++)
#pragma unroll
        for (int half = 0; half < 2; half++) {
            int row = wm + mt * 16 + lr + half * 8;
#pragma unroll
            for (int nt = 0; nt < 8; nt++) {
                int col = wn + nt * 8 + lc * 2;
                atomicAdd(&g_S[row * 128 + col],     acc[mt][nt][half * 2]);
                atomicAdd(&g_S[row * 128 + col + 1], acc[mt][nt][half * 2 + 1]);
            }
        }
}

// scale + TRANSPOSE + fp16
__global__ void k_scaleS(const float* __restrict__ Lambda, const float* __restrict__ gamma) {
    int i = blockIdx.x * blockDim.x + threadIdx.x;
    if (i < KEIG * CC) {
        int c = i >> 7, k = i & 127;
        float l = Lambda[k];
        g_Sth[i] = __float2half(g_S[k * 128 + c] * expf(-gamma[0] * l * l));
    }
}

// ---------------- BN finalize (two BNs in one launch) ----------------
__global__ void k_bnfin2(const float* __restrict__ sums, const float* __restrict__ w1,
                         const float* __restrict__ b1, const float* __restrict__ w2,
                         const float* __restrict__ b2, float* __restrict__ ab)
{
    int t = threadIdx.x;
    int c = t & 127;
    int which = t >> 7;          // 0 -> BN1, 1 -> BN2
    const float* sum = sums + which * 256;
    const float* sq  = sums + which * 256 + 128;
    const float* w = which ? w2 : w1;
    const float* b = which ? b2 : b1;
    float mu  = sum[c] * (1.0f / NN);
    float var = sq[c]  * (1.0f / NN) - mu * mu;
    float aa = w[c] * rsqrtf(var + BN_EPS);
    ab[which * 256 + c]       = aa;
    ab[which * 256 + 128 + c] = b[c] - mu * aa;
}

__global__ void k_bnfin(const float* __restrict__ sum, const float* __restrict__ sq,
                        const float* __restrict__ w, const float* __restrict__ b,
                        float* __restrict__ a, float* __restrict__ bs)
{
    int c = threadIdx.x;
    float mu  = sum[c] * (1.0f / NN);
    float var = sq[c]  * (1.0f / NN) - mu * mu;
    float aa = w[c] * rsqrtf(var + BN_EPS);
    a[c]  = aa;
    bs[c] = b[c] - mu * aa;
}

__global__ void k_combine(const float* __restrict__ pre, const float* __restrict__ h2,
                          float* __restrict__ out0)
{
    int i = blockIdx.x * blockDim.x + threadIdx.x;
    int col4 = (i & 31) * 4;
    float4 p = ((const float4*)pre)[i];
    float4 q = ((const float4*)h2)[i];
    float4 a1 = *(const float4*)&g_ab[col4];
    float4 b1 = *(const float4*)&g_ab[128 + col4];
    float4 a2 = *(const float4*)&g_ab[256 + col4];
    float4 b2 = *(const float4*)&g_ab[384 + col4];
    float4 rv;
    rv.x = fmaf(p.x, a1.x, b1.x) + fmaf(q.x, a2.x, b2.x);
    rv.y = fmaf(p.y, a1.y, b1.y) + fmaf(q.y, a2.y, b2.y);
    rv.z = fmaf(p.z, a1.z, b1.z) + fmaf(q.z, a2.z, b2.z);
    rv.w = fmaf(p.w, a1.w, b1.w) + fmaf(q.w, a2.w, b2.w);
    ((float4*)out0)[i] = rv;
}

__global__ void k_final(const float* __restrict__ X, float* __restrict__ out) {
    int i = blockIdx.x * blockDim.x + threadIdx.x;
    int col4 = (i & 31) * 4;
    float4 v = ((const float4*)X)[i];
    float4 a3 = *(const float4*)&g_ab[512 + col4];
    float4 b3 = *(const float4*)&g_ab[640 + col4];
    float4 rv;
    rv.x = fmaf(v.x, a3.x, b3.x); rv.y = fmaf(v.y, a3.y, b3.y);
    rv.z = fmaf(v.z, a3.z, b3.z); rv.w = fmaf(v.w, a3.w, b3.w);
    ((float4*)out)[i] = rv;
}

// ---------------- fused flash attention (fp16 mma, shuffle-free P->A) --------
#define KS_STR 40   // halves per key row: 32 d + 8 pad
#define VS_STR 136  // halves per d row: 128 keys + 8 pad
__global__ __launch_bounds__(256, 2) void k_flash(const float* __restrict__ qkv,
                                                  float* __restrict__ out)
{
    __shared__ __half Ks[128 * KS_STR];   // [key][d]
    __shared__ __half Vs[32 * VS_STR];    // [d][key]
    int bh = blockIdx.y;
    int b = bh >> 2, h = bh & 3;
    int i0 = blockIdx.x * 128;
    int tid = threadIdx.x;
    int warp = tid >> 5, lane = tid & 31;
    int lr = lane >> 2, lc = lane & 3;
    const unsigned FULL = 0xffffffffu;
    const float scl = 0.17677669529663687f;

    // Q fragments (fp16): 2 k-chunks of 16
    const float* qb = qkv + (size_t)(b * NGR + i0 + warp * 16) * 384 + h * DH;
    uint32_t qf[2][4];
#pragma unroll
    for (int kc = 0; kc < 2; kc++) {
        qf[kc][0] = packh2(qb[(size_t)lr * 384 + kc * 16 + 2 * lc],
                           qb[(size_t)lr * 384 + kc * 16 + 2 * lc + 1]);
        qf[kc][1] = packh2(qb[(size_t)(lr + 8) * 384 + kc * 16 + 2 * lc],
                           qb[(size_t)(lr + 8) * 384 + kc * 16 + 2 * lc + 1]);
        qf[kc][2] = packh2(qb[(size_t)lr * 384 + kc * 16 + 2 * lc + 8],
                           qb[(size_t)lr * 384 + kc * 16 + 2 * lc + 9]);
        qf[kc][3] = packh2(qb[(size_t)(lr + 8) * 384 + kc * 16 + 2 * lc + 8],
                           qb[(size_t)(lr + 8) * 384 + kc * 16 + 2 * lc + 9]);
    }

    float m0 = -1e30f, m1 = -1e30f, l0 = 0.f, l1 = 0.f;
    float o[4][4];
#pragma unroll
    for (int nt = 0; nt < 4; nt++)
#pragma unroll
        for (int q = 0; q < 4; q++) o[nt][q] = 0.f;

    for (int j0 = 0; j0 < NGR; j0 += 128) {
        __syncthreads();
        const float* kb = qkv + (size_t)(b * NGR + j0) * 384 + 128 + h * DH;
        const float* vb = qkv + (size_t)(b * NGR + j0) * 384 + 256 + h * DH;
        {
            int key = tid >> 1, part = tid & 1;       // 16 d per (key,part)
            const float* kp = kb + (size_t)key * 384 + part * 16;
            const float* vp = vb + (size_t)key * 384 + part * 16;
#pragma unroll
            for (int i = 0; i < 8; i++) {
                float2 kv = *(const float2*)&kp[2 * i];
                *(uint32_t*)&Ks[key * KS_STR + part * 16 + 2 * i] = packh2(kv.x, kv.y);
            }
#pragma unroll
            for (int i = 0; i < 16; i++)
                Vs[(part * 16 + i) * VS_STR + key] = __float2half(vp[i]);
        }
        __syncthreads();

        // S = Q K^T (fp16)
        float s[16][4];
#pragma unroll
        for (int g = 0; g < 16; g++)
#pragma unroll
            for (int q = 0; q < 4; q++) s[g][q] = 0.f;
#pragma unroll
        for (int kc = 0; kc < 2; kc++) {
#pragma unroll
            for (int g = 0; g < 16; g++) {
                int c = g * 8 + lr;
                uint32_t b0 = *(const uint32_t*)&Ks[c * KS_STR + kc * 16 + 2 * lc];
                uint32_t b1 = *(const uint32_t*)&Ks[c * KS_STR + kc * 16 + 2 * lc + 8];
                MMA_F16(s[g][0], s[g][1], s[g][2], s[g][3],
                        qf[kc][0], qf[kc][1], qf[kc][2], qf[kc][3], b0, b1);
            }
        }

        // online softmax update (row lr -> s[g][0..1], row lr+8 -> s[g][2..3])
        float mn0 = m0, mn1 = m1;
#pragma unroll
        for (int g = 0; g < 16; g++) {
            s[g][0] *= scl; s[g][1] *= scl; s[g][2] *= scl; s[g][3] *= scl;
            mn0 = fmaxf(mn0, fmaxf(s[g][0], s[g][1]));
            mn1 = fmaxf(mn1, fmaxf(s[g][2], s[g][3]));
        }
        mn0 = fmaxf(mn0, __shfl_xor_sync(FULL, mn0, 1));
        mn0 = fmaxf(mn0, __shfl_xor_sync(FULL, mn0, 2));
        mn1 = fmaxf(mn1, __shfl_xor_sync(FULL, mn1, 1));
        mn1 = fmaxf(mn1, __shfl_xor_sync(FULL, mn1, 2));
        float al0 = __expf(m0 - mn0);
        float al1 = __expf(m1 - mn1);
        m0 = mn0; m1 = mn1;
        float rs0 = 0.f, rs1 = 0.f;
#pragma unroll
        for (int g = 0; g < 16; g++) {
            s[g][0] = __expf(s[g][0] - mn0);
            s[g][1] = __expf(s[g][1] - mn0);
            s[g][2] = __expf(s[g][2] - mn1);
            s[g][3] = __expf(s[g][3] - mn1);
            rs0 += s[g][0] + s[g][1];
            rs1 += s[g][2] + s[g][3];
        }
        rs0 += __shfl_xor_sync(FULL, rs0, 1);
        rs0 += __shfl_xor_sync(FULL, rs0, 2);
        rs1 += __shfl_xor_sync(FULL, rs1, 1);
        rs1 += __shfl_xor_sync(FULL, rs1, 2);
        l0 = l0 * al0 + rs0;
        l1 = l1 * al1 + rs1;
#pragma unroll
        for (int nt = 0; nt < 4; nt++) {
            o[nt][0] *= al0; o[nt][1] *= al0;
            o[nt][2] *= al1; o[nt][3] *= al1;
        }

        // O += P @ V : P C-frag pairs ARE fp16 A-frag pairs (no shuffles)
#pragma unroll
        for (int g2 = 0; g2 < 8; g2++) {
            uint32_t a0 = packh2(s[2 * g2][0],     s[2 * g2][1]);
            uint32_t a1 = packh2(s[2 * g2][2],     s[2 * g2][3]);
            uint32_t a2 = packh2(s[2 * g2 + 1][0], s[2 * g2 + 1][1]);
            uint32_t a3 = packh2(s[2 * g2 + 1][2], s[2 * g2 + 1][3]);
#pragma unroll
            for (int nt = 0; nt < 4; nt++) {
                uint32_t b0 = *(const uint32_t*)&Vs[(nt * 8 + lr) * VS_STR + g2 * 16 + 2 * lc];
                uint32_t b1 = *(const uint32_t*)&Vs[(nt * 8 + lr) * VS_STR + g2 * 16 + 2 * lc + 8];
                MMA_F16(o[nt][0], o[nt][1], o[nt][2], o[nt][3],
                        a0, a1, a2, a3, b0, b1);
            }
        }
    }

    float inv0 = 1.0f / l0, inv1 = 1.0f / l1;
    int row0 = b * NGR + i0 + warp * 16 + lr;
#pragma unroll
    for (int nt = 0; nt < 4; nt++) {
        int col = h * DH + nt * 8 + lc * 2;
        *(float2*)&out[(size_t)row0 * CC + col] =
            make_float2(o[nt][0] * inv0, o[nt][1] * inv0);
        *(float2*)&out[(size_t)(row0 + 8) * CC + col] =
            make_float2(o[nt][2] * inv1, o[nt][3] * inv1);
    }
}

// ---------------- host ----------------
static float* symf(const void* p) { return (float*)p; }

extern "C" void kernel_launch(void* const* d_in, const int* in_sizes, int n_in,
                              void* d_out, int out_size)
{
    const float* x      = (const float*)d_in[0];
    const float* U      = (const float*)d_in[1];
    const float* Lambda = (const float*)d_in[2];
    const float* lamMax = (const float*)d_in[3];
    const float* w_spa1 = (const float*)d_in[4];  const float* b_spa1 = (const float*)d_in[5];
    const float* w_spa2 = (const float*)d_in[6];  const float* b_spa2 = (const float*)d_in[7];
    const float* w_spe1 = (const float*)d_in[8];  const float* b_spe1 = (const float*)d_in[9];
    const float* w_spe2 = (const float*)d_in[10]; const float* b_spe2 = (const float*)d_in[11];
    const float* cheb_w = (const float*)d_in[12]; const float* cheb_b = (const float*)d_in[13];
    const float* gamma  = (const float*)d_in[14]; const float* w_proj = (const float*)d_in[15];
    const float* w_qkv  = (const float*)d_in[16]; const float* b_qkv  = (const float*)d_in[17];
    const float* w_out  = (const float*)d_in[18]; const float* b_out  = (const float*)d_in[19];
    const float* mlp_w1 = (const float*)d_in[20]; const float* mlp_b1 = (const float*)d_in[21];
    const float* mlp_w2 = (const float*)d_in[22]; const float* mlp_b2 = (const float*)d_in[23];
    const float* bn1w = (const float*)d_in[24]; const float* bn1b = (const float*)d_in[25];
    const float* bn2w = (const float*)d_in[26]; const float* bn2b = (const float*)d_in[27];
    const float* bn3w = (const float*)d_in[28]; const float* bn3b = (const float*)d_in[29];
    const int*   ei   = (const int*)d_in[30];
    const int* src = ei;
    const int* dst = ei + EE;
    float* out = (float*)d_out;

    void *pBIG, *pHID, *pLOC, *pXSP, *pHPJ, *pATT, *pH2, *pQKV, *pS, *pSth,
         *pOUTD, *pIND, *pSUMS, *pAB, *pWRD;
    cudaGetSymbolAddress(&pBIG, g_big);   cudaGetSymbolAddress(&pHID, g_hid);
    cudaGetSymbolAddress(&pLOC, g_loc);   cudaGetSymbolAddress(&pXSP, g_xspec);
    cudaGetSymbolAddress(&pHPJ, g_hproj); cudaGetSymbolAddress(&pATT, g_att);
    cudaGetSymbolAddress(&pH2, g_h2);     cudaGetSymbolAddress(&pQKV, g_qkv);
    cudaGetSymbolAddress(&pS, g_S);       cudaGetSymbolAddress(&pSth, g_Sth);
    cudaGetSymbolAddress(&pOUTD, g_outdeg); cudaGetSymbolAddress(&pIND, g_indeg);
    cudaGetSymbolAddress(&pSUMS, g_sums);   cudaGetSymbolAddress(&pAB, g_ab);
    cudaGetSymbolAddress(&pWRD, g_wrd);

    float* BIG = symf(pBIG); float* HID = symf(pHID); float* LOC = symf(pLOC);
    float* XSP = symf(pXSP); float* HPJ = symf(pHPJ); float* ATT = symf(pATT);
    float* H2  = symf(pH2);  float* QKV = symf(pQKV); float* SUMS = symf(pSUMS);
    __half* WR = (__half*)pWRD;
    float* HIDa = HID;
    float* HIDb = HID + (size_t)NN * CC;

    static cudaStream_t s2 = 0, s3 = 0;
    static cudaEvent_t evF = 0, evB = 0, evC = 0;
    if (!s2) {
        cudaStreamCreateWithFlags(&s2, cudaStreamNonBlocking);
        cudaStreamCreateWithFlags(&s3, cudaStreamNonBlocking);
        cudaEventCreateWithFlags(&evF, cudaEventDisableTiming);
        cudaEventCreateWithFlags(&evB, cudaEventDisableTiming);
        cudaEventCreateWithFlags(&evC, cudaEventDisableTiming);
    }

    cudaMemsetAsync(pOUTD, 0, NN * sizeof(int));
    cudaMemsetAsync(pIND,  0, NN * sizeof(int));
    cudaMemsetAsync(pS,    0, KEIG * CC * sizeof(float));
    cudaMemsetAsync(pSUMS, 0, 6 * CC * sizeof(float));

    k_trwAll<<<(WTOT + 255) / 256, 256>>>(w_spa1, w_spa2, w_spe1, w_spe2, w_proj,
                                          cheb_w, w_qkv, w_out, mlp_w1, mlp_w2);

    cudaEventRecord(evF, 0);
    cudaStreamWaitEvent(s2, evF, 0);
    cudaStreamWaitEvent(s3, evF, 0);

    auto GEMM = [&](cudaStream_t st, const float* A, const __half* Wh, const float* bias,
                    const float* res, float* C, int M, int Kd, int ldA, int Cout, int ldC,
                    int relu, int accum, float* sums) {
        dim3 g(M / 128, Cout / 128);
        k_gemm<<<g, 256, 0, st>>>(A, Wh, bias, res, C, M, Kd, ldA, Cout, ldC, relu, accum, sums);
    };

    // ---- branch A (stream 0): spatial MLP + prep + Chebyshev ----
    GEMM(0, x, WR + OSPA1, b_spa1, nullptr, HIDa, NN, 128, 128, 128, 128, 1, 0, nullptr);
    GEMM(0, HIDa, WR + OSPA2, b_spa2, nullptr, BIG, NN, 128, 128, 128, 640, 0, 0, nullptr);
    k_count<<<EE / 256, 256>>>(src, dst);
    k_dis<<<NN / 256, 256>>>();
    k_scan1<<<128, 256>>>();
    k_scan2<<<1, 128>>>();
    k_scan3<<<128, 256>>>();
    k_fill<<<EE / 256, 256>>>(src, dst);
    k_cheb<<<NN / 8, 256>>>(BIG, nullptr, BIG + 128, lamMax, 0, 640);
    for (int k = 2; k < KCH; k++)
        k_cheb<<<NN / 8, 256>>>(BIG + (k - 1) * 128, BIG + (k - 2) * 128,
                                BIG + k * 128, lamMax, 1, 640);
    GEMM(0, BIG, WR + OCHEB, nullptr, nullptr, LOC, NN, 640, 640, 128, 128, 0, 0, nullptr);

    // ---- branch B (s2): spectral ----
    GEMM(s2, x, WR + OSPE1, b_spe1, nullptr, HIDb, NN, 128, 128, 128, 128, 1, 0, nullptr);
    GEMM(s2, HIDb, WR + OSPE2, b_spe2, nullptr, XSP, NN, 128, 128, 128, 128, 0, 0, nullptr);
    GEMM(s2, XSP, WR + OPROJ, nullptr, nullptr, HPJ, NN, 128, 128, 128, 128, 0, 0, nullptr);
    k_utgemm_tc<<<NN / 256, 256, 0, s2>>>(U, HPJ);
    k_scaleS<<<(KEIG * CC) / 256, 256, 0, s2>>>(Lambda, gamma);
    cudaEventRecord(evB, s2);

    // ---- branch C (s3): attention ----
    GEMM(s3, x, WR + OQKV, b_qkv, nullptr, QKV, NN, 128, 128, 384, 384, 0, 0, nullptr);
    {
        dim3 gf(NGR / 128, BBG * HH);
        k_flash<<<gf, 256, 0, s3>>>(QKV, ATT);
    }
    GEMM(s3, ATT, WR + OWOUT, b_out, x, H2, NN, 128, 128, 128, 128, 0, 0, SUMS + 256);
    cudaEventRecord(evC, s3);

    // ---- join on stream 0 ----
    cudaStreamWaitEvent(0, evB, 0);
    GEMM(0, U, (__half*)pSth, cheb_b, x, LOC, NN, 128, 128, 128, 128, 0, 1, SUMS);
    cudaStreamWaitEvent(0, evC, 0);

    k_bnfin2<<<1, 256>>>(SUMS, bn1w, bn1b, bn2w, bn2b, symf(pAB));
    k_combine<<<(NN * CC / 4) / 256, 256>>>(LOC, H2, XSP);

    // ---- final MLP with residual (fused BN3 stats) ----
    GEMM(0, XSP, WR + OMLP1, mlp_b1, nullptr, HID, NN, 128, 128, 256, 256, 1, 0, nullptr);
    GEMM(0, HID, WR + OMLP2, mlp_b2, XSP, LOC, NN, 256, 256, 128, 128, 0, 0, SUMS + 512);

    k_bnfin<<<1, 128>>>(SUMS + 512, SUMS + 640, bn3w, bn3b, symf(pAB) + 512, symf(pAB) + 640);
    k_final<<<(NN * CC / 4) / 256, 256>>>(LOC, out);
}

// round 13
// speedup vs baseline: 1.0508x; 1.0038x over previous
#include <cuda_runtime.h>
#include <cuda_fp16.h>
#include <math.h>
#include <stdint.h>

#define NN   32768
#define CC   128
#define EE   524288
#define BBG  64
#define NGR  512
#define HH   4
#define DH   32
#define KEIG 128
#define KCH  5
#define BN_EPS 1e-5f
#define QKV_LD 640

// ---------------- static scratch ----------------
__device__ float g_big [NN * 640];
__device__ float g_fused[NN * 640];       // [spa_hid | spe_hid | qkv]
__device__ float g_hid [NN * 2 * CC];
__device__ float g_loc [NN * CC];
__device__ float g_xspec[NN * CC];
__device__ float g_hproj[NN * CC];
__device__ float g_att [NN * CC];
__device__ float g_h2  [NN * CC];
__device__ float g_S   [KEIG * CC];
__device__ __half g_Sth[KEIG * CC];
__device__ float g_dis [NN];
__device__ int   g_outdeg[NN];
__device__ int   g_indeg [NN];
__device__ int   g_rowptr[NN + 1];
__device__ int   g_cursor[NN];
__device__ int   g_ecol  [EE];
__device__ int   g_blksum[128];
__device__ int   g_blkoff[128];
__device__ float g_sums[6 * CC];
__device__ float g_bfuse[640];

// fp16 TRANSPOSED weights [Cout][Kd]
#define OSPA2 16384
#define OSPE2 49152
#define OPROJ 65536
#define OCHEB 81920
#define OWOUT 212992
#define OMLP1 229376
#define OMLP2 262144
#define OFUSEW 294912
#define WTOT2  376832
__device__ __half g_wrd[WTOT2];

#define MMA_F16(d0,d1,d2,d3,a0,a1,a2,a3,b0,b1)                                \
    asm volatile("mma.sync.aligned.m16n8k16.row.col.f32.f16.f16.f32 "         \
        "{%0,%1,%2,%3}, {%4,%5,%6,%7}, {%8,%9}, {%0,%1,%2,%3};"               \
        : "+f"(d0), "+f"(d1), "+f"(d2), "+f"(d3)                              \
        : "r"(a0), "r"(a1), "r"(a2), "r"(a3), "r"(b0), "r"(b1))

__device__ __forceinline__ float cvt_tf32(float x) {
    float r;
    asm("cvt.rna.tf32.f32 %0, %1;" : "=f"(r) : "f"(x));
    return r;
}
__device__ __forceinline__ float4 cvt_tf32_4(float4 v) {
    v.x = cvt_tf32(v.x); v.y = cvt_tf32(v.y);
    v.z = cvt_tf32(v.z); v.w = cvt_tf32(v.w);
    return v;
}
#define MMA_TF32(d0,d1,d2,d3,a0,a1,a2,a3,b0,b1)                               \
    asm volatile("mma.sync.aligned.m16n8k8.row.col.f32.tf32.tf32.f32 "        \
        "{%0,%1,%2,%3}, {%4,%5,%6,%7}, {%8,%9}, {%0,%1,%2,%3};"               \
        : "+f"(d0), "+f"(d1), "+f"(d2), "+f"(d3)                              \
        : "r"(a0), "r"(a1), "r"(a2), "r"(a3), "r"(b0), "r"(b1))

__device__ __forceinline__ uint32_t packh2(float lo, float hi) {
    __half2 h = __floats2half2_rn(lo, hi);
    return *(uint32_t*)&h;
}

#define CP16(dst32, srcp) \
    asm volatile("cp.async.cg.shared.global [%0], [%1], 16;" :: "r"(dst32), "l"(srcp))
#define CPCOMMIT() asm volatile("cp.async.commit_group;")
#define CPWAIT0()  asm volatile("cp.async.wait_group 0;")
#define CPWAIT1()  asm volatile("cp.async.wait_group 1;")

// ---------------- zero all per-launch accumulators (one launch) --------------
__global__ void k_zero() {
    int i = blockIdx.x * 256 + threadIdx.x;
    if (i < NN) { g_outdeg[i] = 0; g_indeg[i] = 0; }
    if (i < KEIG * CC) g_S[i] = 0.f;
    if (i < 6 * CC) g_sums[i] = 0.f;
}

// ---------------- fused weight transpose+convert + fused root weight ---------
__global__ void k_trwAll(const float* __restrict__ w0, const float* __restrict__ w1,
                         const float* __restrict__ w2, const float* __restrict__ w3,
                         const float* __restrict__ w4, const float* __restrict__ w5,
                         const float* __restrict__ w6, const float* __restrict__ w7,
                         const float* __restrict__ w8, const float* __restrict__ w9,
                         const float* __restrict__ bs1, const float* __restrict__ bs2,
                         const float* __restrict__ bq)
{
    int i = blockIdx.x * 256 + threadIdx.x;
    if (i < 640)
        g_bfuse[i] = (i < 128) ? bs1[i] : (i < 256) ? bs2[i - 128] : bq[i - 256];
    if (i >= WTOT2) return;
    float v;
    if (i >= OFUSEW) {
        int o = i - OFUSEW;
        int c = o >> 7, k = o & 127;
        v = (c < 128) ? w0[k * 128 + c]
          : (c < 256) ? w2[k * 128 + (c - 128)]
                      : w6[k * 384 + (c - 256)];
    } else {
        const float* src; int off, K, C;
        if      (i < OSPA2)  { src = w0; off = 0;      K = 128; C = 128; }
        else if (i < 32768)  { src = w1; off = OSPA2;  K = 128; C = 128; }
        else if (i < OSPE2)  { src = w2; off = 32768;  K = 128; C = 128; }
        else if (i < OPROJ)  { src = w3; off = OSPE2;  K = 128; C = 128; }
        else if (i < OCHEB)  { src = w4; off = OPROJ;  K = 128; C = 128; }
        else if (i < 163840) { src = w5; off = OCHEB;  K = 640; C = 128; }
        else if (i < OWOUT)  { src = w6; off = 163840; K = 128; C = 384; }
        else if (i < OMLP1)  { src = w7; off = OWOUT;  K = 128; C = 128; }
        else if (i < OMLP2)  { src = w8; off = OMLP1;  K = 128; C = 256; }
        else                 { src = w9; off = OMLP2;  K = 256; C = 128; }
        int o = i - off;
        int c = o / K, k = o - c * K;
        v = src[k * C + c];
    }
    g_wrd[i] = __float2half(v);
}

// ---------------- graph preprocessing ----------------
__global__ void k_count(const int* __restrict__ src, const int* __restrict__ dst) {
    int e = blockIdx.x * blockDim.x + threadIdx.x;
    if (e < EE) {
        atomicAdd(&g_outdeg[src[e]], 1);
        atomicAdd(&g_indeg [dst[e]], 1);
    }
}

// scan stage1 + dis
__global__ void k_scan1() {
    __shared__ int sh[256];
    int t = threadIdx.x;
    int i = blockIdx.x * 256 + t;
    {
        int d = g_outdeg[i];
        g_dis[i] = (d > 0) ? rsqrtf((float)d) : 0.0f;
    }
    int v = g_indeg[i];
    sh[t] = v;
    __syncthreads();
#pragma unroll
    for (int off = 1; off < 256; off <<= 1) {
        int u = (t >= off) ? sh[t - off] : 0;
        __syncthreads();
        sh[t] += u;
        __syncthreads();
    }
    g_rowptr[i] = sh[t] - v;
    if (t == 255) g_blksum[blockIdx.x] = sh[255];
}

__global__ void k_scan2() {
    __shared__ int sh[128];
    int t = threadIdx.x;
    int v = g_blksum[t];
    sh[t] = v;
    __syncthreads();
#pragma unroll
    for (int off = 1; off < 128; off <<= 1) {
        int u = (t >= off) ? sh[t - off] : 0;
        __syncthreads();
        sh[t] += u;
        __syncthreads();
    }
    g_blkoff[t] = sh[t] - v;
    if (t == 127) g_rowptr[NN] = sh[127];
}

__global__ void k_scan3() {
    int t = threadIdx.x;
    int i = blockIdx.x * 256 + t;
    int r = g_rowptr[i] + g_blkoff[blockIdx.x];
    g_rowptr[i] = r;
    g_cursor[i] = r;
}

__global__ void k_fill(const int* __restrict__ src, const int* __restrict__ dst) {
    int e = blockIdx.x * blockDim.x + threadIdx.x;
    if (e < EE) {
        int p = atomicAdd(&g_cursor[dst[e]], 1);
        g_ecol[p] = src[e];
    }
}

// ---------------- fp16 GEMM, cp.async double-buffered, 2 CTAs/SM -------------
// reluc: relu applied to cols < reluc
#define AS_STR 20
#define A_WORDS (128 * AS_STR)
#define B_HALVES (128 * 24)
#define B_BYTES  (B_HALVES * 2)
__global__ __launch_bounds__(256, 2) void k_gemm(
    const float* __restrict__ A, const __half* __restrict__ Wh,
    const float* __restrict__ bias, const float* __restrict__ res,
    float* __restrict__ C, int M, int Kd, int ldA, int Cout, int ldC,
    int reluc, int accum, float* __restrict__ sums)
{
    __shared__ float  As[2 * A_WORDS];
    __shared__ __half Bs[2 * B_HALVES];
    int bm = blockIdx.x * 128;
    int bn = blockIdx.y * 128;
    int tid = threadIdx.x;
    int warp = tid >> 5, lane = tid & 31;
    int wm = (warp >> 1) * 32;
    int wn = (warp & 1) * 64;
    int lr = lane >> 2;
    int lc = lane & 3;

    uint32_t asB = (uint32_t)__cvta_generic_to_shared(As);
    uint32_t bsB = (uint32_t)__cvta_generic_to_shared(Bs);
    int aRow = tid >> 2, aC4 = (tid & 3) * 4;
    int bC = tid >> 1, bH = tid & 1;

#define GISSUE(buf, k0) do {                                                        \
    CP16(asB + (uint32_t)((buf) * A_WORDS + aRow * AS_STR + aC4) * 4u,              \
         A + (size_t)(bm + aRow) * ldA + (k0) + aC4);                               \
    CP16(asB + (uint32_t)((buf) * A_WORDS + (aRow + 64) * AS_STR + aC4) * 4u,       \
         A + (size_t)(bm + aRow + 64) * ldA + (k0) + aC4);                          \
    CP16(bsB + (uint32_t)((buf) * B_BYTES + bC * 48 + bH * 16),                     \
         Wh + (size_t)(bn + bC) * Kd + (k0) + bH * 8);                              \
    CPCOMMIT(); } while (0)

    float acc[2][8][4];
#pragma unroll
    for (int i = 0; i < 2; i++)
#pragma unroll
        for (int j = 0; j < 8; j++)
#pragma unroll
            for (int q = 0; q < 4; q++) acc[i][j][q] = 0.0f;

    int niter = Kd >> 4;
    GISSUE(0, 0);
    for (int it = 0; it < niter; it++) {
        const float*  Ac = As + (it & 1) * A_WORDS;
        const __half* Bc = Bs + (it & 1) * B_HALVES;
        if (it + 1 < niter) {
            GISSUE((it + 1) & 1, (it + 1) * 16);
            CPWAIT1();
        } else {
            CPWAIT0();
        }
        __syncthreads();

        uint32_t af[2][4], bf[8][2];
#pragma unroll
        for (int mt = 0; mt < 2; mt++) {
            int r = wm + mt * 16 + lr;
            float2 v0 = *(const float2*)&Ac[r * AS_STR + 2 * lc];
            float2 v1 = *(const float2*)&Ac[(r + 8) * AS_STR + 2 * lc];
            float2 v2 = *(const float2*)&Ac[r * AS_STR + 2 * lc + 8];
            float2 v3 = *(const float2*)&Ac[(r + 8) * AS_STR + 2 * lc + 8];
            af[mt][0] = packh2(v0.x, v0.y);
            af[mt][1] = packh2(v1.x, v1.y);
            af[mt][2] = packh2(v2.x, v2.y);
            af[mt][3] = packh2(v3.x, v3.y);
        }
#pragma unroll
        for (int nt = 0; nt < 8; nt++) {
            int c = wn + nt * 8 + lr;
            bf[nt][0] = *(const uint32_t*)&Bc[c * 24 + 2 * lc];
            bf[nt][1] = *(const uint32_t*)&Bc[c * 24 + 2 * lc + 8];
        }
#pragma unroll
        for (int mt = 0; mt < 2; mt++)
#pragma unroll
            for (int nt = 0; nt < 8; nt++)
                MMA_F16(acc[mt][nt][0], acc[mt][nt][1], acc[mt][nt][2], acc[mt][nt][3],
                        af[mt][0], af[mt][1], af[mt][2], af[mt][3],
                        bf[nt][0], bf[nt][1]);
        __syncthreads();
    }
#undef GISSUE

    float csum[16], csq[16];
#pragma unroll
    for (int t = 0; t < 16; t++) { csum[t] = 0.f; csq[t] = 0.f; }

#pragma unroll
    for (int mt = 0; mt < 2; mt++) {
#pragma unroll
        for (int half = 0; half < 2; half++) {
            int row = bm + wm + mt * 16 + lr + half * 8;
            size_t ro = (size_t)row * ldC;
            size_t rr = (size_t)row * Cout;
#pragma unroll
            for (int nt = 0; nt < 8; nt++) {
                int col = bn + wn + nt * 8 + lc * 2;
                float v0 = acc[mt][nt][half * 2];
                float v1 = acc[mt][nt][half * 2 + 1];
                if (bias) { v0 += bias[col]; v1 += bias[col + 1]; }
                if (res)  { v0 += res[rr + col]; v1 += res[rr + col + 1]; }
                if (accum){ v0 += C[ro + col];  v1 += C[ro + col + 1]; }
                if (col < reluc)     v0 = fmaxf(v0, 0.f);
                if (col + 1 < reluc) v1 = fmaxf(v1, 0.f);
                if (sums) {
                    csum[nt * 2]     += v0; csq[nt * 2]     = fmaf(v0, v0, csq[nt * 2]);
                    csum[nt * 2 + 1] += v1; csq[nt * 2 + 1] = fmaf(v1, v1, csq[nt * 2 + 1]);
                }
                *(float2*)&C[ro + col] = make_float2(v0, v1);
            }
        }
    }

    if (sums) {
        if (tid < 256) As[tid] = 0.f;
        __syncthreads();
#pragma unroll
        for (int t = 0; t < 16; t++) {
            int col = wn + (t >> 1) * 8 + lc * 2 + (t & 1);
            atomicAdd(&As[col], csum[t]);
            atomicAdd(&As[128 + col], csq[t]);
        }
        __syncthreads();
        if (tid < 128) {
            atomicAdd(&sums[tid],       As[tid]);
            atomicAdd(&sums[tid + 128], As[tid + 128]);
        }
    }
}

// ---------------- Chebyshev gather ----------------
__global__ void k_cheb(const float* __restrict__ Vc, const float* __restrict__ Vp,
                       float* __restrict__ Vo, const float* __restrict__ lam,
                       int mode, int ld)
{
    int gw = (blockIdx.x * blockDim.x + threadIdx.x) >> 5;
    int lane = threadIdx.x & 31;
    if (gw >= NN) return;
    float sc = 2.0f / lam[0];
    int beg = g_rowptr[gw], end = g_rowptr[gw + 1];
    float dn = g_dis[gw];
    float4 acc = make_float4(0.f, 0.f, 0.f, 0.f);
    for (int j = beg; j < end; j++) {
        int s = g_ecol[j];
        float w = dn * g_dis[s];
        float4 v = *(const float4*)&Vc[(size_t)s * ld + lane * 4];
        acc.x = fmaf(w, v.x, acc.x);
        acc.y = fmaf(w, v.y, acc.y);
        acc.z = fmaf(w, v.z, acc.z);
        acc.w = fmaf(w, v.w, acc.w);
    }
    float4 vc = *(const float4*)&Vc[(size_t)gw * ld + lane * 4];
    float sm1 = sc - 1.0f;
    float4 r;
    r.x = sm1 * vc.x - sc * acc.x;
    r.y = sm1 * vc.y - sc * acc.y;
    r.z = sm1 * vc.z - sc * acc.z;
    r.w = sm1 * vc.w - sc * acc.w;
    if (mode) {
        float4 vp = *(const float4*)&Vp[(size_t)gw * ld + lane * 4];
        r.x = 2.f * r.x - vp.x; r.y = 2.f * r.y - vp.y;
        r.z = 2.f * r.z - vp.z; r.w = 2.f * r.w - vp.w;
    }
    *(float4*)&Vo[(size_t)gw * ld + lane * 4] = r;
}

// ---------------- S = U^T @ Hp (tf32 mma, atomic accumulate) ----------------
#define US_STR 132
__global__ __launch_bounds__(256, 2) void k_utgemm_tc(const float* __restrict__ U,
                                                      const float* __restrict__ Hp)
{
    __shared__ float Us[16 * US_STR];
    __shared__ float Hs[16 * US_STR];
    int n0 = blockIdx.x * 256;
    int tid = threadIdx.x;
    int warp = tid >> 5, lane = tid & 31;
    int wm = (warp >> 1) * 32, wn = (warp & 1) * 64;
    int lr = lane >> 2, lc = lane & 3;

    float acc[2][8][4];
#pragma unroll
    for (int i = 0; i < 2; i++)
#pragma unroll
        for (int j = 0; j < 8; j++)
#pragma unroll
            for (int q = 0; q < 4; q++) acc[i][j][q] = 0.f;

    for (int nb = 0; nb < 256; nb += 16) {
#pragma unroll
        for (int l = 0; l < 2; l++) {
            int i = tid + l * 256;
            int row = i >> 5, c4 = (i & 31) * 4;
            *(float4*)&Us[row * US_STR + c4] =
                cvt_tf32_4(*(const float4*)&U [(size_t)(n0 + nb + row) * 128 + c4]);
            *(float4*)&Hs[row * US_STR + c4] =
                cvt_tf32_4(*(const float4*)&Hp[(size_t)(n0 + nb + row) * 128 + c4]);
        }
        __syncthreads();
#pragma unroll
        for (int kk = 0; kk < 16; kk += 8) {
            uint32_t af[2][4], bf[8][2];
#pragma unroll
            for (int mt = 0; mt < 2; mt++) {
                int m = wm + mt * 16 + lr;
                af[mt][0] = __float_as_uint(Us[(kk + lc) * US_STR + m]);
                af[mt][1] = __float_as_uint(Us[(kk + lc) * US_STR + m + 8]);
                af[mt][2] = __float_as_uint(Us[(kk + lc + 4) * US_STR + m]);
                af[mt][3] = __float_as_uint(Us[(kk + lc + 4) * US_STR + m + 8]);
            }
#pragma unroll
            for (int nt = 0; nt < 8; nt++) {
                int c = wn + nt * 8 + lr;
                bf[nt][0] = __float_as_uint(Hs[(kk + lc) * US_STR + c]);
                bf[nt][1] = __float_as_uint(Hs[(kk + lc + 4) * US_STR + c]);
            }
#pragma unroll
            for (int mt = 0; mt < 2; mt++)
#pragma unroll
                for (int nt = 0; nt < 8; nt++)
                    MMA_TF32(acc[mt][nt][0], acc[mt][nt][1], acc[mt][nt][2], acc[mt][nt][3],
                             af[mt][0], af[mt][1], af[mt][2], af[mt][3],
                             bf[nt][0], bf[nt][1]);
        }
        __syncthreads();
    }
#pragma unroll
    for (int mt = 0; mt < 2; mt++)
#pragma unroll
        for (int half = 0; half < 2; half++) {
            int row = wm + mt * 16 + lr + half * 8;
#pragma unroll
            for (int nt = 0; nt < 8; nt++) {
                int col = wn + nt * 8 + lc * 2;
                atomicAdd(&g_S[row * 128 + col],     acc[mt][nt][half * 2]);
                atomicAdd(&g_S[row * 128 + col + 1], acc[mt][nt][half * 2 + 1]);
            }
        }
}

__global__ void k_scaleS(const float* __restrict__ Lambda, const float* __restrict__ gamma) {
    int i = blockIdx.x * blockDim.x + threadIdx.x;
    if (i < KEIG * CC) {
        int c = i >> 7, k = i & 127;
        float l = Lambda[k];
        g_Sth[i] = __float2half(g_S[k * 128 + c] * expf(-gamma[0] * l * l));
    }
}

// ---------------- combine with folded BN1/BN2 finalize ----------------
__global__ void k_combine(const float* __restrict__ pre, const float* __restrict__ h2,
                          float* __restrict__ out0, const float* __restrict__ sums,
                          const float* __restrict__ w1, const float* __restrict__ b1,
                          const float* __restrict__ w2, const float* __restrict__ b2)
{
    __shared__ float sAB[512];
    int t = threadIdx.x;
    {
        int c = t & 127;
        int which = t >> 7;
        const float* sum = sums + which * 256;
        const float* sq  = sums + which * 256 + 128;
        const float* w = which ? w2 : w1;
        const float* b = which ? b2 : b1;
        float mu  = sum[c] * (1.0f / NN);
        float var = sq[c]  * (1.0f / NN) - mu * mu;
        float aa = w[c] * rsqrtf(var + BN_EPS);
        sAB[which * 256 + c]       = aa;
        sAB[which * 256 + 128 + c] = b[c] - mu * aa;
    }
    __syncthreads();
    int i = blockIdx.x * 256 + t;
    int col4 = (i & 31) * 4;
    float4 p = ((const float4*)pre)[i];
    float4 q = ((const float4*)h2)[i];
    float4 a1 = *(const float4*)&sAB[col4];
    float4 bb1 = *(const float4*)&sAB[128 + col4];
    float4 a2 = *(const float4*)&sAB[256 + col4];
    float4 bb2 = *(const float4*)&sAB[384 + col4];
    float4 rv;
    rv.x = fmaf(p.x, a1.x, bb1.x) + fmaf(q.x, a2.x, bb2.x);
    rv.y = fmaf(p.y, a1.y, bb1.y) + fmaf(q.y, a2.y, bb2.y);
    rv.z = fmaf(p.z, a1.z, bb1.z) + fmaf(q.z, a2.z, bb2.z);
    rv.w = fmaf(p.w, a1.w, bb1.w) + fmaf(q.w, a2.w, bb2.w);
    ((float4*)out0)[i] = rv;
}

// ---------------- final with folded BN3 finalize ----------------
__global__ void k_final(const float* __restrict__ X, float* __restrict__ out,
                        const float* __restrict__ sums, const float* __restrict__ w3,
                        const float* __restrict__ b3)
{
    __shared__ float sA[128], sB[128];
    int t = threadIdx.x;
    if (t < 128) {
        float mu  = sums[t] * (1.0f / NN);
        float var = sums[128 + t] * (1.0f / NN) - mu * mu;
        float aa = w3[t] * rsqrtf(var + BN_EPS);
        sA[t] = aa;
        sB[t] = b3[t] - mu * aa;
    }
    __syncthreads();
    int i = blockIdx.x * 256 + t;
    int col4 = (i & 31) * 4;
    float4 v = ((const float4*)X)[i];
    float4 a3 = *(const float4*)&sA[col4];
    float4 bb3 = *(const float4*)&sB[col4];
    float4 rv;
    rv.x = fmaf(v.x, a3.x, bb3.x); rv.y = fmaf(v.y, a3.y, bb3.y);
    rv.z = fmaf(v.z, a3.z, bb3.z); rv.w = fmaf(v.w, a3.w, bb3.w);
    ((float4*)out)[i] = rv;
}

// ---------------- fused flash attention (fp16 mma), qkv in fused (ld 640) ----
#define KS_STR 40
#define VS_STR 136
__global__ __launch_bounds__(256, 2) void k_flash(const float* __restrict__ qkv,
                                                  float* __restrict__ out)
{
    __shared__ __half Ks[128 * KS_STR];
    __shared__ __half Vs[32 * VS_STR];
    int bh = blockIdx.y;
    int b = bh >> 2, h = bh & 3;
    int i0 = blockIdx.x * 128;
    int tid = threadIdx.x;
    int warp = tid >> 5, lane = tid & 31;
    int lr = lane >> 2, lc = lane & 3;
    const unsigned FULL = 0xffffffffu;
    const float scl = 0.17677669529663687f;

    const float* qb = qkv + (size_t)(b * NGR + i0 + warp * 16) * QKV_LD + h * DH;
    uint32_t qf[2][4];
#pragma unroll
    for (int kc = 0; kc < 2; kc++) {
        qf[kc][0] = packh2(qb[(size_t)lr * QKV_LD + kc * 16 + 2 * lc],
                           qb[(size_t)lr * QKV_LD + kc * 16 + 2 * lc + 1]);
        qf[kc][1] = packh2(qb[(size_t)(lr + 8) * QKV_LD + kc * 16 + 2 * lc],
                           qb[(size_t)(lr + 8) * QKV_LD + kc * 16 + 2 * lc + 1]);
        qf[kc][2] = packh2(qb[(size_t)lr * QKV_LD + kc * 16 + 2 * lc + 8],
                           qb[(size_t)lr * QKV_LD + kc * 16 + 2 * lc + 9]);
        qf[kc][3] = packh2(qb[(size_t)(lr + 8) * QKV_LD + kc * 16 + 2 * lc + 8],
                           qb[(size_t)(lr + 8) * QKV_LD + kc * 16 + 2 * lc + 9]);
    }

    float m0 = -1e30f, m1 = -1e30f, l0 = 0.f, l1 = 0.f;
    float o[4][4];
#pragma unroll
    for (int nt = 0; nt < 4; nt++)
#pragma unroll
        for (int q = 0; q < 4; q++) o[nt][q] = 0.f;

    for (int j0 = 0; j0 < NGR; j0 += 128) {
        __syncthreads();
        const float* kb = qkv + (size_t)(b * NGR + j0) * QKV_LD + 128 + h * DH;
        const float* vb = qkv + (size_t)(b * NGR + j0) * QKV_LD + 256 + h * DH;
        {
            int key = tid >> 1, part = tid & 1;
            const float* kp = kb + (size_t)key * QKV_LD + part * 16;
            const float* vp = vb + (size_t)key * QKV_LD + part * 16;
#pragma unroll
            for (int i = 0; i < 8; i++) {
                float2 kv = *(const float2*)&kp[2 * i];
                *(uint32_t*)&Ks[key * KS_STR + part * 16 + 2 * i] = packh2(kv.x, kv.y);
            }
#pragma unroll
            for (int i = 0; i < 16; i++)
                Vs[(part * 16 + i) * VS_STR + key] = __float2half(vp[i]);
        }
        __syncthreads();

        float s[16][4];
#pragma unroll
        for (int g = 0; g < 16; g++)
#pragma unroll
            for (int q = 0; q < 4; q++) s[g][q] = 0.f;
#pragma unroll
        for (int kc = 0; kc < 2; kc++) {
#pragma unroll
            for (int g = 0; g < 16; g++) {
                int c = g * 8 + lr;
                uint32_t b0 = *(const uint32_t*)&Ks[c * KS_STR + kc * 16 + 2 * lc];
                uint32_t b1 = *(const uint32_t*)&Ks[c * KS_STR + kc * 16 + 2 * lc + 8];
                MMA_F16(s[g][0], s[g][1], s[g][2], s[g][3],
                        qf[kc][0], qf[kc][1], qf[kc][2], qf[kc][3], b0, b1);
            }
        }

        float mn0 = m0, mn1 = m1;
#pragma unroll
        for (int g = 0; g < 16; g++) {
            s[g][0] *= scl; s[g][1] *= scl; s[g][2] *= scl; s[g][3] *= scl;
            mn0 = fmaxf(mn0, fmaxf(s[g][0], s[g][1]));
            mn1 = fmaxf(mn1, fmaxf(s[g][2], s[g][3]));
        }
        mn0 = fmaxf(mn0, __shfl_xor_sync(FULL, mn0, 1));
        mn0 = fmaxf(mn0, __shfl_xor_sync(FULL, mn0, 2));
        mn1 = fmaxf(mn1, __shfl_xor_sync(FULL, mn1, 1));
        mn1 = fmaxf(mn1, __shfl_xor_sync(FULL, mn1, 2));
        float al0 = __expf(m0 - mn0);
        float al1 = __expf(m1 - mn1);
        m0 = mn0; m1 = mn1;
        float rs0 = 0.f, rs1 = 0.f;
#pragma unroll
        for (int g = 0; g < 16; g++) {
            s[g][0] = __expf(s[g][0] - mn0);
            s[g][1] = __expf(s[g][1] - mn0);
            s[g][2] = __expf(s[g][2] - mn1);
            s[g][3] = __expf(s[g][3] - mn1);
            rs0 += s[g][0] + s[g][1];
            rs1 += s[g][2] + s[g][3];
        }
        rs0 += __shfl_xor_sync(FULL, rs0, 1);
        rs0 += __shfl_xor_sync(FULL, rs0, 2);
        rs1 += __shfl_xor_sync(FULL, rs1, 1);
        rs1 += __shfl_xor_sync(FULL, rs1, 2);
        l0 = l0 * al0 + rs0;
        l1 = l1 * al1 + rs1;
#pragma unroll
        for (int nt = 0; nt < 4; nt++) {
            o[nt][0] *= al0; o[nt][1] *= al0;
            o[nt][2] *= al1; o[nt][3] *= al1;
        }

#pragma unroll
        for (int g2 = 0; g2 < 8; g2++) {
            uint32_t a0 = packh2(s[2 * g2][0],     s[2 * g2][1]);
            uint32_t a1 = packh2(s[2 * g2][2],     s[2 * g2][3]);
            uint32_t a2 = packh2(s[2 * g2 + 1][0], s[2 * g2 + 1][1]);
            uint32_t a3 = packh2(s[2 * g2 + 1][2], s[2 * g2 + 1][3]);
#pragma unroll
            for (int nt = 0; nt < 4; nt++) {
                uint32_t b0 = *(const uint32_t*)&Vs[(nt * 8 + lr) * VS_STR + g2 * 16 + 2 * lc];
                uint32_t b1 = *(const uint32_t*)&Vs[(nt * 8 + lr) * VS_STR + g2 * 16 + 2 * lc + 8];
                MMA_F16(o[nt][0], o[nt][1], o[nt][2], o[nt][3],
                        a0, a1, a2, a3, b0, b1);
            }
        }
    }

    float inv0 = 1.0f / l0, inv1 = 1.0f / l1;
    int row0 = b * NGR + i0 + warp * 16 + lr;
#pragma unroll
    for (int nt = 0; nt < 4; nt++) {
        int col = h * DH + nt * 8 + lc * 2;
        *(float2*)&out[(size_t)row0 * CC + col] =
            make_float2(o[nt][0] * inv0, o[nt][1] * inv0);
        *(float2*)&out[(size_t)(row0 + 8) * CC + col] =
            make_float2(o[nt][2] * inv1, o[nt][3] * inv1);
    }
}

// ---------------- host ----------------
static float* symf(const void* p) { return (float*)p; }

extern "C" void kernel_launch(void* const* d_in, const int* in_sizes, int n_in,
                              void* d_out, int out_size)
{
    const float* x      = (const float*)d_in[0];
    const float* U      = (const float*)d_in[1];
    const float* Lambda = (const float*)d_in[2];
    const float* lamMax = (const float*)d_in[3];
    const float* w_spa1 = (const float*)d_in[4];  const float* b_spa1 = (const float*)d_in[5];
    const float* w_spa2 = (const float*)d_in[6];  const float* b_spa2 = (const float*)d_in[7];
    const float* w_spe1 = (const float*)d_in[8];  const float* b_spe1 = (const float*)d_in[9];
    const float* w_spe2 = (const float*)d_in[10]; const float* b_spe2 = (const float*)d_in[11];
    const float* cheb_w = (const float*)d_in[12]; const float* cheb_b = (const float*)d_in[13];
    const float* gamma  = (const float*)d_in[14]; const float* w_proj = (const float*)d_in[15];
    const float* w_qkv  = (const float*)d_in[16]; const float* b_qkv  = (const float*)d_in[17];
    const float* w_out  = (const float*)d_in[18]; const float* b_out  = (const float*)d_in[19];
    const float* mlp_w1 = (const float*)d_in[20]; const float* mlp_b1 = (const float*)d_in[21];
    const float* mlp_w2 = (const float*)d_in[22]; const float* mlp_b2 = (const float*)d_in[23];
    const float* bn1w = (const float*)d_in[24]; const float* bn1b = (const float*)d_in[25];
    const float* bn2w = (const float*)d_in[26]; const float* bn2b = (const float*)d_in[27];
    const float* bn3w = (const float*)d_in[28]; const float* bn3b = (const float*)d_in[29];
    const int*   ei   = (const int*)d_in[30];
    const int* src = ei;
    const int* dst = ei + EE;
    float* out = (float*)d_out;

    void *pBIG, *pFUS, *pHID, *pLOC, *pXSP, *pHPJ, *pATT, *pH2, *pSth,
         *pSUMS, *pWRD, *pBF;
    cudaGetSymbolAddress(&pBIG, g_big);   cudaGetSymbolAddress(&pFUS, g_fused);
    cudaGetSymbolAddress(&pHID, g_hid);   cudaGetSymbolAddress(&pLOC, g_loc);
    cudaGetSymbolAddress(&pXSP, g_xspec); cudaGetSymbolAddress(&pHPJ, g_hproj);
    cudaGetSymbolAddress(&pATT, g_att);   cudaGetSymbolAddress(&pH2, g_h2);
    cudaGetSymbolAddress(&pSth, g_Sth);   cudaGetSymbolAddress(&pSUMS, g_sums);
    cudaGetSymbolAddress(&pWRD, g_wrd);   cudaGetSymbolAddress(&pBF, g_bfuse);

    float* BIG = symf(pBIG); float* FUS = symf(pFUS); float* HID = symf(pHID);
    float* LOC = symf(pLOC); float* XSP = symf(pXSP); float* HPJ = symf(pHPJ);
    float* ATT = symf(pATT); float* H2  = symf(pH2);  float* SUMS = symf(pSUMS);
    __half* WR = (__half*)pWRD;

    static cudaStream_t s2 = 0, s3 = 0;
    static cudaEvent_t evF = 0, evB = 0, evC = 0;
    if (!s2) {
        cudaStreamCreateWithFlags(&s2, cudaStreamNonBlocking);
        cudaStreamCreateWithFlags(&s3, cudaStreamNonBlocking);
        cudaEventCreateWithFlags(&evF, cudaEventDisableTiming);
        cudaEventCreateWithFlags(&evB, cudaEventDisableTiming);
        cudaEventCreateWithFlags(&evC, cudaEventDisableTiming);
    }

    auto GEMM = [&](cudaStream_t st, const float* A, const __half* Wh, const float* bias,
                    const float* res, float* C, int M, int Kd, int ldA, int Cout, int ldC,
                    int reluc, int accum, float* sums) {
        dim3 g(M / 128, Cout / 128);
        k_gemm<<<g, 256, 0, st>>>(A, Wh, bias, res, C, M, Kd, ldA, Cout, ldC,
                                  reluc, accum, sums);
    };

    // ---- head (stream 0): zero + weights + fused root GEMM ----
    k_zero<<<(NN + 255) / 256, 256>>>();
    k_trwAll<<<(WTOT2 + 255) / 256, 256>>>(w_spa1, w_spa2, w_spe1, w_spe2, w_proj,
                                           cheb_w, w_qkv, w_out, mlp_w1, mlp_w2,
                                           b_spa1, b_spe1, b_qkv);
    GEMM(0, x, WR + OFUSEW, symf(pBF), nullptr, FUS, NN, 128, 128, 640, 640, 256, 0, nullptr);
    cudaEventRecord(evF, 0);
    cudaStreamWaitEvent(s2, evF, 0);
    cudaStreamWaitEvent(s3, evF, 0);

    // ---- branch A (stream 0): spa2 + prep + Chebyshev ----
    GEMM(0, FUS, WR + OSPA2, b_spa2, nullptr, BIG, NN, 128, 640, 128, 640, 0, 0, nullptr);
    k_count<<<EE / 256, 256>>>(src, dst);
    k_scan1<<<128, 256>>>();
    k_scan2<<<1, 128>>>();
    k_scan3<<<128, 256>>>();
    k_fill<<<EE / 256, 256>>>(src, dst);
    k_cheb<<<NN / 8, 256>>>(BIG, nullptr, BIG + 128, lamMax, 0, 640);
    for (int k = 2; k < KCH; k++)
        k_cheb<<<NN / 8, 256>>>(BIG + (k - 1) * 128, BIG + (k - 2) * 128,
                                BIG + k * 128, lamMax, 1, 640);
    GEMM(0, BIG, WR + OCHEB, nullptr, nullptr, LOC, NN, 640, 640, 128, 128, 0, 0, nullptr);

    // ---- branch B (s2): spectral ----
    GEMM(s2, FUS + 128, WR + OSPE2, b_spe2, nullptr, XSP, NN, 128, 640, 128, 128, 0, 0, nullptr);
    GEMM(s2, XSP, WR + OPROJ, nullptr, nullptr, HPJ, NN, 128, 128, 128, 128, 0, 0, nullptr);
    k_utgemm_tc<<<NN / 256, 256, 0, s2>>>(U, HPJ);
    k_scaleS<<<(KEIG * CC) / 256, 256, 0, s2>>>(Lambda, gamma);
    cudaEventRecord(evB, s2);

    // ---- branch C (s3): attention ----
    {
        dim3 gf(NGR / 128, BBG * HH);
        k_flash<<<gf, 256, 0, s3>>>(FUS + 256, ATT);
    }
    GEMM(s3, ATT, WR + OWOUT, b_out, x, H2, NN, 128, 128, 128, 128, 0, 0, SUMS + 256);
    cudaEventRecord(evC, s3);

    // ---- join on stream 0 ----
    cudaStreamWaitEvent(0, evB, 0);
    GEMM(0, U, (__half*)pSth, cheb_b, x, LOC, NN, 128, 128, 128, 128, 0, 1, SUMS);
    cudaStreamWaitEvent(0, evC, 0);

    k_combine<<<(NN * CC / 4) / 256, 256>>>(LOC, H2, XSP, SUMS, bn1w, bn1b, bn2w, bn2b);

    // ---- final MLP with residual (fused BN3 stats) ----
    GEMM(0, XSP, WR + OMLP1, mlp_b1, nullptr, HID, NN, 128, 128, 256, 256, 256, 0, nullptr);
    GEMM(0, HID, WR + OMLP2, mlp_b2, XSP, LOC, NN, 256, 256, 128, 128, 0, 0, SUMS + 512);

    k_final<<<(NN * CC / 4) / 256, 256>>>(LOC, out, SUMS + 512, bn3w, bn3b);
}